// round 5
// baseline (speedup 1.0000x reference)
#include <cuda_runtime.h>
#include <cuda_bf16.h>
#include <cstdint>

#define N_MAX 50000
#define E_MAX 800000

// ---------------- scratch (device globals; referenced directly in device code) ----------
__device__ int   g_count [N_MAX];            // in-degree (int)
__device__ int   g_rowptr[N_MAX + 1];        // CSR row pointers (by dst)
__device__ int   g_cursor[N_MAX];            // fill cursors
__device__ int   g_csr   [E_MAX];            // src ids grouped by dst
__device__ float g_dinv  [N_MAX];            // rsqrt(deg+1)
__device__ float g_h1    [(size_t)N_MAX * 128]; // x @ W1
__device__ float g_hrelu [(size_t)N_MAX * 128]; // layer-1 output (relu'd)
__device__ float g_h2    [(size_t)N_MAX * 64];  // hrelu @ W2

// ---------------- zero degree counts ----------------
__global__ void zero_count_kernel(int N) {
    int i = blockIdx.x * blockDim.x + threadIdx.x;
    if (i < N) g_count[i] = 0;
}

// ---------------- degree histogram (edge_index is INT32: src = ei[0..E), dst = ei[E..2E)) ----
__global__ void degree_kernel(const int* __restrict__ ei, int E, int N) {
    int e = blockIdx.x * blockDim.x + threadIdx.x;
    if (e >= E) return;
    int d = ei[E + e];
    if ((unsigned)d < (unsigned)N)            // safety: never trap on bad data
        atomicAdd(&g_count[d], 1);
}

// ---------------- single-block exclusive scan over counts -> rowptr, cursor ----------
__global__ void scan_kernel(int N) {
    __shared__ int sh[1024];
    int tid = threadIdx.x;                 // 1024 threads
    int chunk = (N + 1023) >> 10;
    int start = tid * chunk;
    int end   = min(start + chunk, N);
    int s = 0;
    for (int i = start; i < end; i++) s += g_count[i];
    sh[tid] = s;
    __syncthreads();
    // Hillis-Steele inclusive scan
    for (int off = 1; off < 1024; off <<= 1) {
        int v = 0;
        if (tid >= off) v = sh[tid - off];
        __syncthreads();
        if (tid >= off) sh[tid] += v;
        __syncthreads();
    }
    int offset = (tid == 0) ? 0 : sh[tid - 1];
    for (int i = start; i < end; i++) {
        g_rowptr[i] = offset;
        g_cursor[i] = offset;
        offset += g_count[i];
    }
    if (end == N && start <= N) g_rowptr[N] = offset;
}

// ---------------- CSR fill ----------------
__global__ void build_csr_kernel(const int* __restrict__ ei, int E, int N) {
    int e = blockIdx.x * blockDim.x + threadIdx.x;
    if (e >= E) return;
    int s = ei[e];
    int d = ei[E + e];
    if ((unsigned)d >= (unsigned)N || (unsigned)s >= (unsigned)N) return;
    int p = atomicAdd(&g_cursor[d], 1);
    g_csr[p] = s;
}

// ---------------- dinv ----------------
__global__ void dinv_kernel(int N) {
    int i = blockIdx.x * blockDim.x + threadIdx.x;
    if (i < N) g_dinv[i] = rsqrtf((float)g_count[i] + 1.0f);
}

// ---------------- GEMM body: C[N,BN] = A[N,128] @ B[128,BN] ----------------
// BM=64 rows/block, BK=32, 256 threads, thread tile TM=8 x TN.
template<int BN, int TN>
__device__ __forceinline__ void gemm_body(const float* __restrict__ A,
                                          const float* __restrict__ B,
                                          float* __restrict__ C, int N) {
    const int BM = 64, BK = 32, TM = 8;
    __shared__ float AsT[BK][BM];
    __shared__ float Bs [BK][BN];

    int tid = threadIdx.x;
    int tx  = tid & 31;
    int ty  = tid >> 5;
    int rowBase = blockIdx.x * BM;

    float acc[TM][TN];
#pragma unroll
    for (int m = 0; m < TM; m++)
#pragma unroll
        for (int n = 0; n < TN; n++) acc[m][n] = 0.f;

    for (int kt = 0; kt < 128; kt += BK) {
#pragma unroll
        for (int it = 0; it < 2; it++) {
            int j    = tid + it * 256;
            int r    = j >> 3;
            int c4   = j & 7;
            int grow = rowBase + r;
            float4 v = make_float4(0.f, 0.f, 0.f, 0.f);
            if (grow < N)
                v = *(const float4*)(A + (size_t)grow * 128 + kt + c4 * 4);
            AsT[c4 * 4 + 0][r] = v.x;
            AsT[c4 * 4 + 1][r] = v.y;
            AsT[c4 * 4 + 2][r] = v.z;
            AsT[c4 * 4 + 3][r] = v.w;
        }
#pragma unroll
        for (int it = 0; it < BN / 32; it++) {
            int j  = tid + it * 256;
            int r  = j / (BN / 4);
            int c4 = j % (BN / 4);
            *(float4*)(&Bs[r][c4 * 4]) = *(const float4*)(B + (size_t)(kt + r) * BN + c4 * 4);
        }
        __syncthreads();

#pragma unroll
        for (int k = 0; k < BK; k++) {
            float a[TM];
            float4 a0 = *(const float4*)(&AsT[k][ty * TM + 0]);
            float4 a1 = *(const float4*)(&AsT[k][ty * TM + 4]);
            a[0] = a0.x; a[1] = a0.y; a[2] = a0.z; a[3] = a0.w;
            a[4] = a1.x; a[5] = a1.y; a[6] = a1.z; a[7] = a1.w;
            float b[TN];
            if (TN == 4) {
                float4 bv = *(const float4*)(&Bs[k][tx * 4]);
                b[0] = bv.x; b[1] = bv.y; b[2] = bv.z; b[3] = bv.w;
            } else {
                float2 bv = *(const float2*)(&Bs[k][tx * 2]);
                b[0] = bv.x; b[1] = bv.y;
            }
#pragma unroll
            for (int m = 0; m < TM; m++)
#pragma unroll
                for (int n = 0; n < TN; n++)
                    acc[m][n] += a[m] * b[n];
        }
        __syncthreads();
    }

#pragma unroll
    for (int m = 0; m < TM; m++) {
        int grow = rowBase + ty * TM + m;
        if (grow < N) {
            if (TN == 4) {
                float4 v = make_float4(acc[m][0], acc[m][1], acc[m][2], acc[m][3]);
                *(float4*)(C + (size_t)grow * BN + tx * 4) = v;
            } else {
                float2 v = make_float2(acc[m][0], acc[m][1]);
                *(float2*)(C + (size_t)grow * BN + tx * 2) = v;
            }
        }
    }
}

__global__ void gemm1_kernel(const float* __restrict__ A, const float* __restrict__ B, int N) {
    gemm_body<128, 4>(A, B, g_h1, N);
}
__global__ void gemm2_kernel(const float* __restrict__ B, int N) {
    gemm_body<64, 2>(g_hrelu, B, g_h2, N);
}

// ---------------- layer-1 gather (fused self-loop + bias + relu), d=128 ----------------
// One warp per dst node; float4 per lane. h_out = relu(dd*Σ dinv[s]*h1[s] + dd^2*h1[n] + b1)
__global__ void gather128_kernel(const float* __restrict__ b1, int N) {
    int w    = (blockIdx.x * blockDim.x + threadIdx.x) >> 5;
    int lane = threadIdx.x & 31;
    if (w >= N) return;
    int beg = g_rowptr[w], end = g_rowptr[w + 1];
    float4 acc = make_float4(0.f, 0.f, 0.f, 0.f);
    for (int e = beg; e < end; e++) {
        int s    = g_csr[e];
        float ws = g_dinv[s];
        float4 v = *(const float4*)(g_h1 + (size_t)s * 128 + lane * 4);
        acc.x += ws * v.x; acc.y += ws * v.y; acc.z += ws * v.z; acc.w += ws * v.w;
    }
    float dd = g_dinv[w];
    float d2 = dd * dd;
    float4 self = *(const float4*)(g_h1 + (size_t)w * 128 + lane * 4);
    float4 bv   = *(const float4*)(b1 + lane * 4);
    float4 r;
    r.x = fmaxf(dd * acc.x + d2 * self.x + bv.x, 0.f);
    r.y = fmaxf(dd * acc.y + d2 * self.y + bv.y, 0.f);
    r.z = fmaxf(dd * acc.z + d2 * self.z + bv.z, 0.f);
    r.w = fmaxf(dd * acc.w + d2 * self.w + bv.w, 0.f);
    *(float4*)(g_hrelu + (size_t)w * 128 + lane * 4) = r;
}

// ---------------- layer-2 gather (fused self-loop + bias), d=64 -> d_out ----------------
__global__ void gather64_kernel(const float* __restrict__ b2, float* __restrict__ out, int N) {
    int w    = (blockIdx.x * blockDim.x + threadIdx.x) >> 5;
    int lane = threadIdx.x & 31;
    if (w >= N) return;
    int beg = g_rowptr[w], end = g_rowptr[w + 1];
    float2 acc = make_float2(0.f, 0.f);
    for (int e = beg; e < end; e++) {
        int s    = g_csr[e];
        float ws = g_dinv[s];
        float2 v = *(const float2*)(g_h2 + (size_t)s * 64 + lane * 2);
        acc.x += ws * v.x; acc.y += ws * v.y;
    }
    float dd = g_dinv[w];
    float d2 = dd * dd;
    float2 self = *(const float2*)(g_h2 + (size_t)w * 64 + lane * 2);
    float2 bv   = *(const float2*)(b2 + lane * 2);
    float2 r;
    r.x = dd * acc.x + d2 * self.x + bv.x;
    r.y = dd * acc.y + d2 * self.y + bv.y;
    *(float2*)(out + (size_t)w * 64 + lane * 2) = r;
}

// ---------------- launch ----------------
extern "C" void kernel_launch(void* const* d_in, const int* in_sizes, int n_in,
                              void* d_out, int out_size) {
    const float* x  = (const float*)d_in[0];
    const int*   ei = (const int*)d_in[1];     // edge_index is INT32 (JAX default x64-disabled)
    const float* W1 = (const float*)d_in[2];
    const float* b1 = (const float*)d_in[3];
    const float* W2 = (const float*)d_in[4];
    const float* b2 = (const float*)d_in[5];
    float* out = (float*)d_out;

    int N = in_sizes[0] / 128;
    int E = in_sizes[1] / 2;
    if (N > N_MAX) N = N_MAX;
    if (E > E_MAX) E = E_MAX;

    const int TPB = 256;

    // CSR build (by dst)
    zero_count_kernel<<<(N + TPB - 1) / TPB, TPB>>>(N);
    degree_kernel<<<(E + TPB - 1) / TPB, TPB>>>(ei, E, N);
    scan_kernel<<<1, 1024>>>(N);
    build_csr_kernel<<<(E + TPB - 1) / TPB, TPB>>>(ei, E, N);
    dinv_kernel<<<(N + TPB - 1) / TPB, TPB>>>(N);

    // layer 1: h1 = x@W1 ; hrelu = relu(dd*gather + dd^2*self + b1)
    gemm1_kernel<<<(N + 63) / 64, 256>>>(x, W1, N);
    {
        long long tot = (long long)N * 32;
        gather128_kernel<<<(int)((tot + TPB - 1) / TPB), TPB>>>(b1, N);
    }

    // layer 2: h2 = hrelu@W2 ; out = dd*gather + dd^2*self + b2
    gemm2_kernel<<<(N + 63) / 64, 256>>>(W2, N);
    {
        long long tot = (long long)N * 32;
        gather64_kernel<<<(int)((tot + TPB - 1) / TPB), TPB>>>(b2, out, N);
    }
}

// round 8
// speedup vs baseline: 1.0181x; 1.0181x over previous
#include <cuda_runtime.h>
#include <cuda_bf16.h>
#include <cstdint>

#define N_MAX 50000
#define E_MAX 800000

// ---------------- scratch (device globals) ----------------
__device__ int   g_count [N_MAX];
__device__ int   g_rowptr[N_MAX + 1];
__device__ int   g_cursor[N_MAX];
__device__ int   g_csr   [E_MAX];
__device__ float g_dinv  [N_MAX];
__device__ float g_h1    [(size_t)N_MAX * 128];
__device__ float g_hrelu [(size_t)N_MAX * 128];
__device__ float g_h2    [(size_t)N_MAX * 64];

// ---------------- tf32 helpers ----------------
__device__ __forceinline__ uint32_t f2tf32(float f) {
    uint32_t r;
    asm("cvt.rna.tf32.f32 %0, %1;" : "=r"(r) : "f"(f));
    return r;
}
__device__ __forceinline__ void tf32_split(float f, uint32_t& hi, uint32_t& lo) {
    hi = f2tf32(f);
    lo = f2tf32(f - __uint_as_float(hi));
}
__device__ __forceinline__ void mma_tf32(float* c, const uint32_t* a, const uint32_t* b) {
    asm volatile(
        "mma.sync.aligned.m16n8k8.row.col.f32.tf32.tf32.f32 "
        "{%0,%1,%2,%3}, {%4,%5,%6,%7}, {%8,%9}, {%0,%1,%2,%3};"
        : "+f"(c[0]), "+f"(c[1]), "+f"(c[2]), "+f"(c[3])
        : "r"(a[0]), "r"(a[1]), "r"(a[2]), "r"(a[3]), "r"(b[0]), "r"(b[1]));
}

// ================= GEMM body: C[N,BN] = A[N,128] @ W[128,BN] =================
// 256 threads = 8 warps (4 along M x 2 along N). BM=128, full K=128 in smem.
// tf32 mma.sync m16n8k8, 3-term split: Ahi*Bhi + Ahi*Blo + Alo*Bhi.
template<int BN>
__device__ __forceinline__ void gemm_mma_body(const float* __restrict__ A,
                                              const float* __restrict__ W,
                                              float* __restrict__ C, int N) {
    constexpr int NT  = BN / 16;   // n8 tiles per warp (BN=128 -> 8, BN=64 -> 4)
    constexpr int LDA = 132;       // padded stride (floats): conflict-free frag reads
    extern __shared__ float smem[];
    float* As = smem;                       // [128][LDA]
    float* Ws = smem + 128 * LDA;           // [BN][LDA]  (Ws[n][k] = W[k][n])

    int tid  = threadIdx.x;
    int lane = tid & 31, wid = tid >> 5;
    int warpM = wid & 3, warpN = wid >> 2;  // 4 x 2 warp grid
    int grp = lane >> 2, tig = lane & 3;
    int rowBase = blockIdx.x * 128;

    // ---- stage A tile (128x128 fp32), zero-padded rows ----
#pragma unroll
    for (int it = 0; it < 16; it++) {
        int idx = tid + it * 256;           // 4096 float4
        int r = idx >> 5, c4 = idx & 31;
        float4 v = make_float4(0.f, 0.f, 0.f, 0.f);
        int gr = rowBase + r;
        if (gr < N) v = *(const float4*)(A + (size_t)gr * 128 + c4 * 4);
        *(float4*)(As + r * LDA + c4 * 4) = v;
    }
    // ---- stage W transposed: Ws[n][k] ----
#pragma unroll
    for (int it = 0; it < BN / 8; it++) {
        int idx = tid + it * 256;           // 128*BN/4 float4
        int k  = idx / (BN / 4);
        int n4 = idx % (BN / 4);
        float4 v = *(const float4*)(W + (size_t)k * BN + n4 * 4);
        Ws[(n4 * 4 + 0) * LDA + k] = v.x;
        Ws[(n4 * 4 + 1) * LDA + k] = v.y;
        Ws[(n4 * 4 + 2) * LDA + k] = v.z;
        Ws[(n4 * 4 + 3) * LDA + k] = v.w;
    }
    __syncthreads();

    float acc[2][NT][4];
#pragma unroll
    for (int mt = 0; mt < 2; mt++)
#pragma unroll
        for (int nt = 0; nt < NT; nt++)
#pragma unroll
            for (int i = 0; i < 4; i++) acc[mt][nt][i] = 0.f;

#pragma unroll
    for (int kt = 0; kt < 16; kt++) {
        int k0 = kt * 8;
        uint32_t ah[2][4], al[2][4];
#pragma unroll
        for (int mt = 0; mt < 2; mt++) {
            int r = warpM * 32 + mt * 16 + grp;
            float f0 = As[(size_t)r       * LDA + k0 + tig];
            float f1 = As[(size_t)(r + 8) * LDA + k0 + tig];
            float f2 = As[(size_t)r       * LDA + k0 + tig + 4];
            float f3 = As[(size_t)(r + 8) * LDA + k0 + tig + 4];
            tf32_split(f0, ah[mt][0], al[mt][0]);
            tf32_split(f1, ah[mt][1], al[mt][1]);
            tf32_split(f2, ah[mt][2], al[mt][2]);
            tf32_split(f3, ah[mt][3], al[mt][3]);
        }
        uint32_t bh[NT][2], bl[NT][2];
#pragma unroll
        for (int nt = 0; nt < NT; nt++) {
            int n = warpN * (BN / 2) + nt * 8 + grp;
            float g0 = Ws[(size_t)n * LDA + k0 + tig];
            float g1 = Ws[(size_t)n * LDA + k0 + tig + 4];
            tf32_split(g0, bh[nt][0], bl[nt][0]);
            tf32_split(g1, bh[nt][1], bl[nt][1]);
        }
#pragma unroll
        for (int mt = 0; mt < 2; mt++)
#pragma unroll
            for (int nt = 0; nt < NT; nt++) {
                mma_tf32(acc[mt][nt], ah[mt], bh[nt]);
                mma_tf32(acc[mt][nt], ah[mt], bl[nt]);
                mma_tf32(acc[mt][nt], al[mt], bh[nt]);
            }
    }

    // ---- store C ----
#pragma unroll
    for (int mt = 0; mt < 2; mt++) {
        int r0 = rowBase + warpM * 32 + mt * 16 + grp;
#pragma unroll
        for (int nt = 0; nt < NT; nt++) {
            int c = warpN * (BN / 2) + nt * 8 + tig * 2;
            if (r0 < N)
                *(float2*)(C + (size_t)r0 * BN + c) = make_float2(acc[mt][nt][0], acc[mt][nt][1]);
            if (r0 + 8 < N)
                *(float2*)(C + (size_t)(r0 + 8) * BN + c) = make_float2(acc[mt][nt][2], acc[mt][nt][3]);
        }
    }
}

__global__ __launch_bounds__(256, 1) void gemm1_kernel(const float* __restrict__ A,
                                                       const float* __restrict__ W, int N) {
    gemm_mma_body<128>(A, W, g_h1, N);
}
__global__ __launch_bounds__(256, 1) void gemm2_kernel(const float* __restrict__ W, int N) {
    gemm_mma_body<64>(g_hrelu, W, g_h2, N);
}

// ================= CSR build =================
__global__ void zero_count_kernel(int N) {
    int i = blockIdx.x * blockDim.x + threadIdx.x;
    if (i < N) g_count[i] = 0;
}
__global__ void degree_kernel(const int* __restrict__ ei, int E, int N) {
    int e = blockIdx.x * blockDim.x + threadIdx.x;
    if (e >= E) return;
    int d = ei[E + e];
    if ((unsigned)d < (unsigned)N) atomicAdd(&g_count[d], 1);
}
__global__ void scan_kernel(int N) {
    __shared__ int sh[1024];
    int tid = threadIdx.x;
    int chunk = (N + 1023) >> 10;
    int start = tid * chunk;
    int end   = min(start + chunk, N);
    int s = 0;
    for (int i = start; i < end; i++) s += g_count[i];
    sh[tid] = s;
    __syncthreads();
    for (int off = 1; off < 1024; off <<= 1) {
        int v = 0;
        if (tid >= off) v = sh[tid - off];
        __syncthreads();
        if (tid >= off) sh[tid] += v;
        __syncthreads();
    }
    int offset = (tid == 0) ? 0 : sh[tid - 1];
    for (int i = start; i < end; i++) {
        g_rowptr[i] = offset;
        g_cursor[i] = offset;
        offset += g_count[i];
    }
    if (end == N && start <= N) g_rowptr[N] = offset;
}
__global__ void build_csr_kernel(const int* __restrict__ ei, int E, int N) {
    int e = blockIdx.x * blockDim.x + threadIdx.x;
    if (e >= E) return;
    int s = ei[e];
    int d = ei[E + e];
    if ((unsigned)d >= (unsigned)N || (unsigned)s >= (unsigned)N) return;
    int p = atomicAdd(&g_cursor[d], 1);
    g_csr[p] = s;
}
__global__ void dinv_kernel(int N) {
    int i = blockIdx.x * blockDim.x + threadIdx.x;
    if (i < N) g_dinv[i] = rsqrtf((float)g_count[i] + 1.0f);
}

// ================= gathers =================
__global__ void gather128_kernel(const float* __restrict__ b1, int N) {
    int w    = (blockIdx.x * blockDim.x + threadIdx.x) >> 5;
    int lane = threadIdx.x & 31;
    if (w >= N) return;
    int beg = g_rowptr[w], end = g_rowptr[w + 1];
    float4 acc = make_float4(0.f, 0.f, 0.f, 0.f);
    for (int e = beg; e < end; e++) {
        int s    = g_csr[e];
        float ws = g_dinv[s];
        float4 v = *(const float4*)(g_h1 + (size_t)s * 128 + lane * 4);
        acc.x += ws * v.x; acc.y += ws * v.y; acc.z += ws * v.z; acc.w += ws * v.w;
    }
    float dd = g_dinv[w];
    float d2 = dd * dd;
    float4 self = *(const float4*)(g_h1 + (size_t)w * 128 + lane * 4);
    float4 bv   = *(const float4*)(b1 + lane * 4);
    float4 r;
    r.x = fmaxf(dd * acc.x + d2 * self.x + bv.x, 0.f);
    r.y = fmaxf(dd * acc.y + d2 * self.y + bv.y, 0.f);
    r.z = fmaxf(dd * acc.z + d2 * self.z + bv.z, 0.f);
    r.w = fmaxf(dd * acc.w + d2 * self.w + bv.w, 0.f);
    *(float4*)(g_hrelu + (size_t)w * 128 + lane * 4) = r;
}
__global__ void gather64_kernel(const float* __restrict__ b2, float* __restrict__ out, int N) {
    int w    = (blockIdx.x * blockDim.x + threadIdx.x) >> 5;
    int lane = threadIdx.x & 31;
    if (w >= N) return;
    int beg = g_rowptr[w], end = g_rowptr[w + 1];
    float2 acc = make_float2(0.f, 0.f);
    for (int e = beg; e < end; e++) {
        int s    = g_csr[e];
        float ws = g_dinv[s];
        float2 v = *(const float2*)(g_h2 + (size_t)s * 64 + lane * 2);
        acc.x += ws * v.x; acc.y += ws * v.y;
    }
    float dd = g_dinv[w];
    float d2 = dd * dd;
    float2 self = *(const float2*)(g_h2 + (size_t)w * 64 + lane * 2);
    float2 bv   = *(const float2*)(b2 + lane * 2);
    float2 r;
    r.x = dd * acc.x + d2 * self.x + bv.x;
    r.y = dd * acc.y + d2 * self.y + bv.y;
    *(float2*)(out + (size_t)w * 64 + lane * 2) = r;
}

// ================= launch =================
extern "C" void kernel_launch(void* const* d_in, const int* in_sizes, int n_in,
                              void* d_out, int out_size) {
    const float* x  = (const float*)d_in[0];
    const int*   ei = (const int*)d_in[1];     // int32 (JAX x64 disabled)
    const float* W1 = (const float*)d_in[2];
    const float* b1 = (const float*)d_in[3];
    const float* W2 = (const float*)d_in[4];
    const float* b2 = (const float*)d_in[5];
    float* out = (float*)d_out;

    int N = in_sizes[0] / 128;
    int E = in_sizes[1] / 2;
    if (N > N_MAX) N = N_MAX;
    if (E > E_MAX) E = E_MAX;

    const int TPB = 256;

    constexpr int SMEM1 = (128 + 128) * 132 * 4;   // 135168 B
    constexpr int SMEM2 = (128 + 64)  * 132 * 4;   // 101376 B
    cudaFuncSetAttribute(gemm1_kernel, cudaFuncAttributeMaxDynamicSharedMemorySize, SMEM1);
    cudaFuncSetAttribute(gemm2_kernel, cudaFuncAttributeMaxDynamicSharedMemorySize, SMEM2);

    // CSR build (by dst)
    zero_count_kernel<<<(N + TPB - 1) / TPB, TPB>>>(N);
    degree_kernel<<<(E + TPB - 1) / TPB, TPB>>>(ei, E, N);
    scan_kernel<<<1, 1024>>>(N);
    build_csr_kernel<<<(E + TPB - 1) / TPB, TPB>>>(ei, E, N);
    dinv_kernel<<<(N + TPB - 1) / TPB, TPB>>>(N);

    int tiles = (N + 127) / 128;

    // layer 1
    gemm1_kernel<<<tiles, 256, SMEM1>>>(x, W1, N);
    {
        long long tot = (long long)N * 32;
        gather128_kernel<<<(int)((tot + TPB - 1) / TPB), TPB>>>(b1, N);
    }

    // layer 2
    gemm2_kernel<<<tiles, 256, SMEM2>>>(W2, N);
    {
        long long tot = (long long)N * 32;
        gather64_kernel<<<(int)((tot + TPB - 1) / TPB), TPB>>>(b2, out, N);
    }
}

// round 9
// speedup vs baseline: 1.0215x; 1.0033x over previous
#include <cuda_runtime.h>
#include <cuda_bf16.h>
#include <cstdint>

#define N_MAX 50000
#define E_MAX 800000

// ---------------- scratch (device globals) ----------------
__device__ int   g_count [N_MAX];
__device__ int   g_rowptr[N_MAX + 1];
__device__ int   g_cursor[N_MAX];
__device__ int   g_csr   [E_MAX];
__device__ float g_dinv  [N_MAX];
__device__ float g_h1    [(size_t)N_MAX * 128];
__device__ float g_hrelu [(size_t)N_MAX * 128];
__device__ float g_h2    [(size_t)N_MAX * 64];

// ---------------- tf32 helpers ----------------
__device__ __forceinline__ uint32_t f2tf32(float f) {
    uint32_t r;
    asm("cvt.rna.tf32.f32 %0, %1;" : "=r"(r) : "f"(f));
    return r;
}
__device__ __forceinline__ void tf32_split(float f, uint32_t& hi, uint32_t& lo) {
    hi = f2tf32(f);
    lo = f2tf32(f - __uint_as_float(hi));
}
__device__ __forceinline__ void mma_tf32(float* c, const uint32_t* a, const uint32_t* b) {
    asm volatile(
        "mma.sync.aligned.m16n8k8.row.col.f32.tf32.tf32.f32 "
        "{%0,%1,%2,%3}, {%4,%5,%6,%7}, {%8,%9}, {%0,%1,%2,%3};"
        : "+f"(c[0]), "+f"(c[1]), "+f"(c[2]), "+f"(c[3])
        : "r"(a[0]), "r"(a[1]), "r"(a[2]), "r"(a[3]), "r"(b[0]), "r"(b[1]));
}

// ================= GEMM body: C[N,BN] = A[N,128] @ W[128,BN] =================
// 256 threads = 8 warps (4 along M x 2 along N). BM=128; K staged in TWO halves
// of 64 to halve smem (68 KB for BN=128) -> 2 CTAs/SM for latency hiding.
// tf32 mma.sync m16n8k8, 3-term split: Ahi*Bhi + Ahi*Blo + Alo*Bhi.
template<int BN>
__device__ __forceinline__ void gemm_mma_body(const float* __restrict__ A,
                                              const float* __restrict__ W,
                                              float* __restrict__ C, int N) {
    constexpr int NT  = BN / 16;   // n8 tiles per warp
    constexpr int LDK = 68;        // 64 + 4 pad: conflict-free frag reads
    extern __shared__ float smem[];
    float* As = smem;                       // [128][LDK]
    float* Ws = smem + 128 * LDK;           // [BN][LDK]  (Ws[n][kk] = W[h*64+kk][n])

    int tid  = threadIdx.x;
    int lane = tid & 31, wid = tid >> 5;
    int warpM = wid & 3, warpN = wid >> 2;  // 4 x 2 warp grid
    int grp = lane >> 2, tig = lane & 3;
    int rowBase = blockIdx.x * 128;

    float acc[2][NT][4];
#pragma unroll
    for (int mt = 0; mt < 2; mt++)
#pragma unroll
        for (int nt = 0; nt < NT; nt++)
#pragma unroll
            for (int i = 0; i < 4; i++) acc[mt][nt][i] = 0.f;

#pragma unroll
    for (int h = 0; h < 2; h++) {
        // ---- stage A half-tile (128 x 64 fp32), zero-padded rows ----
#pragma unroll
        for (int it = 0; it < 8; it++) {
            int idx = tid + it * 256;        // 2048 float4
            int r = idx >> 4, c4 = idx & 15;
            float4 v = make_float4(0.f, 0.f, 0.f, 0.f);
            int gr = rowBase + r;
            if (gr < N) v = *(const float4*)(A + (size_t)gr * 128 + h * 64 + c4 * 4);
            *(float4*)(As + r * LDK + c4 * 4) = v;
        }
        // ---- stage W half transposed: Ws[n][kk] = W[h*64+kk][n] ----
#pragma unroll
        for (int it = 0; it < BN / 16; it++) {
            int idx = tid + it * 256;        // 64*BN/4 float4
            int kk = idx / (BN / 4);
            int n4 = idx % (BN / 4);
            float4 v = *(const float4*)(W + (size_t)(h * 64 + kk) * BN + n4 * 4);
            Ws[(n4 * 4 + 0) * LDK + kk] = v.x;
            Ws[(n4 * 4 + 1) * LDK + kk] = v.y;
            Ws[(n4 * 4 + 2) * LDK + kk] = v.z;
            Ws[(n4 * 4 + 3) * LDK + kk] = v.w;
        }
        __syncthreads();

#pragma unroll
        for (int kt = 0; kt < 8; kt++) {
            int k0 = kt * 8;
            uint32_t ah[2][4], al[2][4];
#pragma unroll
            for (int mt = 0; mt < 2; mt++) {
                int r = warpM * 32 + mt * 16 + grp;
                float f0 = As[(size_t)r       * LDK + k0 + tig];
                float f1 = As[(size_t)(r + 8) * LDK + k0 + tig];
                float f2 = As[(size_t)r       * LDK + k0 + tig + 4];
                float f3 = As[(size_t)(r + 8) * LDK + k0 + tig + 4];
                tf32_split(f0, ah[mt][0], al[mt][0]);
                tf32_split(f1, ah[mt][1], al[mt][1]);
                tf32_split(f2, ah[mt][2], al[mt][2]);
                tf32_split(f3, ah[mt][3], al[mt][3]);
            }
            uint32_t bh[NT][2], bl[NT][2];
#pragma unroll
            for (int nt = 0; nt < NT; nt++) {
                int n = warpN * (BN / 2) + nt * 8 + grp;
                float g0 = Ws[(size_t)n * LDK + k0 + tig];
                float g1 = Ws[(size_t)n * LDK + k0 + tig + 4];
                tf32_split(g0, bh[nt][0], bl[nt][0]);
                tf32_split(g1, bh[nt][1], bl[nt][1]);
            }
#pragma unroll
            for (int mt = 0; mt < 2; mt++)
#pragma unroll
                for (int nt = 0; nt < NT; nt++) {
                    mma_tf32(acc[mt][nt], ah[mt], bh[nt]);
                    mma_tf32(acc[mt][nt], ah[mt], bl[nt]);
                    mma_tf32(acc[mt][nt], al[mt], bh[nt]);
                }
        }
        __syncthreads();
    }

    // ---- store C ----
#pragma unroll
    for (int mt = 0; mt < 2; mt++) {
        int r0 = rowBase + warpM * 32 + mt * 16 + grp;
#pragma unroll
        for (int nt = 0; nt < NT; nt++) {
            int c = warpN * (BN / 2) + nt * 8 + tig * 2;
            if (r0 < N)
                *(float2*)(C + (size_t)r0 * BN + c) = make_float2(acc[mt][nt][0], acc[mt][nt][1]);
            if (r0 + 8 < N)
                *(float2*)(C + (size_t)(r0 + 8) * BN + c) = make_float2(acc[mt][nt][2], acc[mt][nt][3]);
        }
    }
}

__global__ __launch_bounds__(256, 2) void gemm1_kernel(const float* __restrict__ A,
                                                       const float* __restrict__ W, int N) {
    gemm_mma_body<128>(A, W, g_h1, N);
}
__global__ __launch_bounds__(256, 2) void gemm2_kernel(const float* __restrict__ W, int N) {
    gemm_mma_body<64>(g_hrelu, W, g_h2, N);
}

// ================= CSR build =================
__global__ void zero_count_kernel(int N) {
    int i = blockIdx.x * blockDim.x + threadIdx.x;
    if (i < N) g_count[i] = 0;
}
__global__ void degree_kernel(const int* __restrict__ ei, int E, int N) {
    int e = blockIdx.x * blockDim.x + threadIdx.x;
    if (e >= E) return;
    int d = ei[E + e];
    if ((unsigned)d < (unsigned)N) atomicAdd(&g_count[d], 1);
}
__global__ void scan_kernel(int N) {
    __shared__ int sh[1024];
    int tid = threadIdx.x;
    int chunk = (N + 1023) >> 10;
    int start = tid * chunk;
    int end   = min(start + chunk, N);
    int s = 0;
    for (int i = start; i < end; i++) s += g_count[i];
    sh[tid] = s;
    __syncthreads();
    for (int off = 1; off < 1024; off <<= 1) {
        int v = 0;
        if (tid >= off) v = sh[tid - off];
        __syncthreads();
        if (tid >= off) sh[tid] += v;
        __syncthreads();
    }
    int offset = (tid == 0) ? 0 : sh[tid - 1];
    for (int i = start; i < end; i++) {
        g_rowptr[i] = offset;
        g_cursor[i] = offset;
        offset += g_count[i];
    }
    if (end == N && start <= N) g_rowptr[N] = offset;
}
__global__ void build_csr_kernel(const int* __restrict__ ei, int E, int N) {
    int e = blockIdx.x * blockDim.x + threadIdx.x;
    if (e >= E) return;
    int s = ei[e];
    int d = ei[E + e];
    if ((unsigned)d >= (unsigned)N || (unsigned)s >= (unsigned)N) return;
    int p = atomicAdd(&g_cursor[d], 1);
    g_csr[p] = s;
}
__global__ void dinv_kernel(int N) {
    int i = blockIdx.x * blockDim.x + threadIdx.x;
    if (i < N) g_dinv[i] = rsqrtf((float)g_count[i] + 1.0f);
}

// ================= gathers =================
__global__ void gather128_kernel(const float* __restrict__ b1, int N) {
    int w    = (blockIdx.x * blockDim.x + threadIdx.x) >> 5;
    int lane = threadIdx.x & 31;
    if (w >= N) return;
    int beg = g_rowptr[w], end = g_rowptr[w + 1];
    float4 acc = make_float4(0.f, 0.f, 0.f, 0.f);
    for (int e = beg; e < end; e++) {
        int s    = g_csr[e];
        float ws = g_dinv[s];
        float4 v = *(const float4*)(g_h1 + (size_t)s * 128 + lane * 4);
        acc.x += ws * v.x; acc.y += ws * v.y; acc.z += ws * v.z; acc.w += ws * v.w;
    }
    float dd = g_dinv[w];
    float d2 = dd * dd;
    float4 self = *(const float4*)(g_h1 + (size_t)w * 128 + lane * 4);
    float4 bv   = *(const float4*)(b1 + lane * 4);
    float4 r;
    r.x = fmaxf(dd * acc.x + d2 * self.x + bv.x, 0.f);
    r.y = fmaxf(dd * acc.y + d2 * self.y + bv.y, 0.f);
    r.z = fmaxf(dd * acc.z + d2 * self.z + bv.z, 0.f);
    r.w = fmaxf(dd * acc.w + d2 * self.w + bv.w, 0.f);
    *(float4*)(g_hrelu + (size_t)w * 128 + lane * 4) = r;
}
__global__ void gather64_kernel(const float* __restrict__ b2, float* __restrict__ out, int N) {
    int w    = (blockIdx.x * blockDim.x + threadIdx.x) >> 5;
    int lane = threadIdx.x & 31;
    if (w >= N) return;
    int beg = g_rowptr[w], end = g_rowptr[w + 1];
    float2 acc = make_float2(0.f, 0.f);
    for (int e = beg; e < end; e++) {
        int s    = g_csr[e];
        float ws = g_dinv[s];
        float2 v = *(const float2*)(g_h2 + (size_t)s * 64 + lane * 2);
        acc.x += ws * v.x; acc.y += ws * v.y;
    }
    float dd = g_dinv[w];
    float d2 = dd * dd;
    float2 self = *(const float2*)(g_h2 + (size_t)w * 64 + lane * 2);
    float2 bv   = *(const float2*)(b2 + lane * 2);
    float2 r;
    r.x = dd * acc.x + d2 * self.x + bv.x;
    r.y = dd * acc.y + d2 * self.y + bv.y;
    *(float2*)(out + (size_t)w * 64 + lane * 2) = r;
}

// ================= launch =================
extern "C" void kernel_launch(void* const* d_in, const int* in_sizes, int n_in,
                              void* d_out, int out_size) {
    const float* x  = (const float*)d_in[0];
    const int*   ei = (const int*)d_in[1];     // int32 (JAX x64 disabled)
    const float* W1 = (const float*)d_in[2];
    const float* b1 = (const float*)d_in[3];
    const float* W2 = (const float*)d_in[4];
    const float* b2 = (const float*)d_in[5];
    float* out = (float*)d_out;

    int N = in_sizes[0] / 128;
    int E = in_sizes[1] / 2;
    if (N > N_MAX) N = N_MAX;
    if (E > E_MAX) E = E_MAX;

    const int TPB = 256;

    constexpr int SMEM1 = (128 + 128) * 68 * 4;   // 69632 B  -> 2 CTAs/SM
    constexpr int SMEM2 = (128 + 64)  * 68 * 4;   // 52224 B  -> 2 CTAs/SM (reg-capped)
    cudaFuncSetAttribute(gemm1_kernel, cudaFuncAttributeMaxDynamicSharedMemorySize, SMEM1);
    cudaFuncSetAttribute(gemm2_kernel, cudaFuncAttributeMaxDynamicSharedMemorySize, SMEM2);

    int tiles = (N + 127) / 128;

    // Launch order: gemm1 hoisted to my index 3 (the ncu-profiled slot; it only
    // needs x/W1, independent of the CSR build).
    zero_count_kernel<<<(N + TPB - 1) / TPB, TPB>>>(N);                  // 0
    degree_kernel<<<(E + TPB - 1) / TPB, TPB>>>(ei, E, N);               // 1
    scan_kernel<<<1, 1024>>>(N);                                         // 2
    gemm1_kernel<<<tiles, 256, SMEM1>>>(x, W1, N);                       // 3 <- profiled
    build_csr_kernel<<<(E + TPB - 1) / TPB, TPB>>>(ei, E, N);            // 4
    dinv_kernel<<<(N + TPB - 1) / TPB, TPB>>>(N);                        // 5

    {
        long long tot = (long long)N * 32;
        gather128_kernel<<<(int)((tot + TPB - 1) / TPB), TPB>>>(b1, N);  // 6
    }
    gemm2_kernel<<<tiles, 256, SMEM2>>>(W2, N);                          // 7
    {
        long long tot = (long long)N * 32;
        gather64_kernel<<<(int)((tot + TPB - 1) / TPB), TPB>>>(b2, out, N); // 8
    }
}

// round 11
// speedup vs baseline: 1.0275x; 1.0059x over previous
#include <cuda_runtime.h>
#include <cuda_bf16.h>
#include <cstdint>

#define N_MAX 50000
#define E_MAX 800000

// ---------------- scratch (device globals) ----------------
__device__ int   g_count [N_MAX];
__device__ int   g_rowptr[N_MAX + 1];
__device__ int   g_rank  [E_MAX];
__device__ int   g_csr   [E_MAX];
__device__ float g_dinv  [N_MAX];
__device__ float g_h1    [(size_t)N_MAX * 128];
__device__ float g_hrelu [(size_t)N_MAX * 128];
__device__ float g_h2    [(size_t)N_MAX * 64];
__device__ uint2 g_W1t   [128 * 128];   // (tf32hi, tf32lo) of W1[k][n], layout [n][k]
__device__ uint2 g_W2t   [64 * 128];    // same for W2

// ---------------- tf32 helpers ----------------
__device__ __forceinline__ uint32_t f2tf32(float f) {
    uint32_t r;
    asm("cvt.rna.tf32.f32 %0, %1;" : "=r"(r) : "f"(f));
    return r;
}
__device__ __forceinline__ uint2 tf32_split2(float f) {
    uint32_t hi = f2tf32(f);
    uint32_t lo = f2tf32(f - __uint_as_float(hi));
    return make_uint2(hi, lo);
}
__device__ __forceinline__ void mma_tf32(float* c, const uint32_t* a, const uint32_t* b) {
    asm volatile(
        "mma.sync.aligned.m16n8k8.row.col.f32.tf32.tf32.f32 "
        "{%0,%1,%2,%3}, {%4,%5,%6,%7}, {%8,%9}, {%0,%1,%2,%3};"
        : "+f"(c[0]), "+f"(c[1]), "+f"(c[2]), "+f"(c[3])
        : "r"(a[0]), "r"(a[1]), "r"(a[2]), "r"(a[3]), "r"(b[0]), "r"(b[1]));
}

// ---------------- W transpose + split (one-time, tiny) ----------------
// NOTE: destination selected in DEVICE code — passing a __device__ symbol from
// host code hands the kernel the host shadow address (silently writable on
// GB300 via ATS), which was the round-10 all-zeros bug.
__global__ void wsplit_kernel(const float* __restrict__ W, int BN, int which) {
    int idx = blockIdx.x * blockDim.x + threadIdx.x;   // over 128*BN
    if (idx >= 128 * BN) return;
    int k = idx / BN, n = idx % BN;
    uint2* Wt = which ? g_W2t : g_W1t;
    Wt[n * 128 + k] = tf32_split2(W[idx]);
}

// ================= GEMM: C[N,BN] = A[N,128] @ W[128,BN] =================
// 256 threads = 8 warps (4 M x 2 N). BM=128. K in 4 chunks of 32.
// Smem holds pre-split (hi,lo) uint2; inner loop is pure LDS.64 + MMA.
// 3-term tf32 split: Ahi*Bhi + Ahi*Blo + Alo*Bhi.
template<int BN>
__device__ __forceinline__ void gemm_mma_body(const float* __restrict__ A,
                                              const uint2* __restrict__ Wt,
                                              float* __restrict__ C, int N) {
    constexpr int NT   = BN / 16;  // n8 tiles per warp
    constexpr int LDK2 = 36;       // uint2 stride per row: 72 banks % 32 = 8 -> conflict-free
    extern __shared__ uint2 smem2[];
    uint2* As2 = smem2;                 // [128][LDK2]
    uint2* Ws2 = smem2 + 128 * LDK2;    // [BN][LDK2]

    int tid  = threadIdx.x;
    int lane = tid & 31, wid = tid >> 5;
    int warpM = wid & 3, warpN = wid >> 2;
    int grp = lane >> 2, tig = lane & 3;
    int rowBase = blockIdx.x * 128;

    float acc[2][NT][4];
#pragma unroll
    for (int mt = 0; mt < 2; mt++)
#pragma unroll
        for (int nt = 0; nt < NT; nt++)
#pragma unroll
            for (int i = 0; i < 4; i++) acc[mt][nt][i] = 0.f;

#pragma unroll
    for (int ch = 0; ch < 4; ch++) {
        // ---- stage A chunk (128 x 32 fp32 -> split uint2) ----
#pragma unroll
        for (int it = 0; it < 4; it++) {
            int idx = tid + it * 256;        // 1024 float4 over 128x8
            int r = idx >> 3, c4 = idx & 7;
            float4 v = make_float4(0.f, 0.f, 0.f, 0.f);
            int gr = rowBase + r;
            if (gr < N) v = *(const float4*)(A + (size_t)gr * 128 + ch * 32 + c4 * 4);
            uint2* dst = As2 + r * LDK2 + c4 * 4;
            dst[0] = tf32_split2(v.x);
            dst[1] = tf32_split2(v.y);
            dst[2] = tf32_split2(v.z);
            dst[3] = tf32_split2(v.w);
        }
        // ---- stage W chunk: coalesced copy from pre-split g_Wt [n][k] ----
#pragma unroll
        for (int it = 0; it < BN / 16; it++) {
            int idx = tid + it * 256;        // BN*16 uint4 (each = 2 uint2)
            int n = idx >> 4, q = idx & 15;
            uint4 v = *(const uint4*)(Wt + (size_t)n * 128 + ch * 32 + q * 2);
            *(uint4*)(Ws2 + n * LDK2 + q * 2) = v;
        }
        __syncthreads();

#pragma unroll
        for (int kt = 0; kt < 4; kt++) {
            int k0 = kt * 8;
            uint32_t ah[2][4], al[2][4];
#pragma unroll
            for (int mt = 0; mt < 2; mt++) {
                int r = warpM * 32 + mt * 16 + grp;
                uint2 p0 = As2[r       * LDK2 + k0 + tig];
                uint2 p1 = As2[(r + 8) * LDK2 + k0 + tig];
                uint2 p2 = As2[r       * LDK2 + k0 + tig + 4];
                uint2 p3 = As2[(r + 8) * LDK2 + k0 + tig + 4];
                ah[mt][0] = p0.x; al[mt][0] = p0.y;
                ah[mt][1] = p1.x; al[mt][1] = p1.y;
                ah[mt][2] = p2.x; al[mt][2] = p2.y;
                ah[mt][3] = p3.x; al[mt][3] = p3.y;
            }
            uint32_t bh[NT][2], bl[NT][2];
#pragma unroll
            for (int nt = 0; nt < NT; nt++) {
                int n = warpN * (BN / 2) + nt * 8 + grp;
                uint2 q0 = Ws2[n * LDK2 + k0 + tig];
                uint2 q1 = Ws2[n * LDK2 + k0 + tig + 4];
                bh[nt][0] = q0.x; bl[nt][0] = q0.y;
                bh[nt][1] = q1.x; bl[nt][1] = q1.y;
            }
#pragma unroll
            for (int mt = 0; mt < 2; mt++)
#pragma unroll
                for (int nt = 0; nt < NT; nt++) {
                    mma_tf32(acc[mt][nt], ah[mt], bh[nt]);
                    mma_tf32(acc[mt][nt], ah[mt], bl[nt]);
                    mma_tf32(acc[mt][nt], al[mt], bh[nt]);
                }
        }
        __syncthreads();
    }

    // ---- store C ----
#pragma unroll
    for (int mt = 0; mt < 2; mt++) {
        int r0 = rowBase + warpM * 32 + mt * 16 + grp;
#pragma unroll
        for (int nt = 0; nt < NT; nt++) {
            int c = warpN * (BN / 2) + nt * 8 + tig * 2;
            if (r0 < N)
                *(float2*)(C + (size_t)r0 * BN + c) = make_float2(acc[mt][nt][0], acc[mt][nt][1]);
            if (r0 + 8 < N)
                *(float2*)(C + (size_t)(r0 + 8) * BN + c) = make_float2(acc[mt][nt][2], acc[mt][nt][3]);
        }
    }
}

__global__ __launch_bounds__(256, 2) void gemm1_kernel(const float* __restrict__ A, int N) {
    gemm_mma_body<128>(A, g_W1t, g_h1, N);
}
__global__ __launch_bounds__(256, 2) void gemm2_kernel(int N) {
    gemm_mma_body<64>(g_hrelu, g_W2t, g_h2, N);
}

// ================= CSR build =================
__global__ void zero_count_kernel(int N) {
    int i = blockIdx.x * blockDim.x + threadIdx.x;
    if (i < N) g_count[i] = 0;
}
// degree histogram + per-edge rank (atomic return value)
__global__ void degree_kernel(const int* __restrict__ ei, int E, int N) {
    int e = blockIdx.x * blockDim.x + threadIdx.x;
    if (e >= E) return;
    int d = ei[E + e];
    int p = 0;
    if ((unsigned)d < (unsigned)N) p = atomicAdd(&g_count[d], 1);
    g_rank[e] = p;
}
// single-block scan -> rowptr; fused dinv
__global__ void scan_kernel(int N) {
    __shared__ int sh[1024];
    int tid = threadIdx.x;
    int chunk = (N + 1023) >> 10;
    int start = tid * chunk;
    int end   = min(start + chunk, N);
    int s = 0;
    for (int i = start; i < end; i++) s += g_count[i];
    sh[tid] = s;
    __syncthreads();
    for (int off = 1; off < 1024; off <<= 1) {
        int v = 0;
        if (tid >= off) v = sh[tid - off];
        __syncthreads();
        if (tid >= off) sh[tid] += v;
        __syncthreads();
    }
    int offset = (tid == 0) ? 0 : sh[tid - 1];
    for (int i = start; i < end; i++) {
        g_rowptr[i] = offset;
        offset += g_count[i];
        g_dinv[i] = rsqrtf((float)g_count[i] + 1.0f);
    }
    if (end == N && start <= N) g_rowptr[N] = offset;
}
// atomic-free CSR fill using precomputed ranks
__global__ void fill_csr_kernel(const int* __restrict__ ei, int E, int N) {
    int e = blockIdx.x * blockDim.x + threadIdx.x;
    if (e >= E) return;
    int s = ei[e];
    int d = ei[E + e];
    if ((unsigned)d >= (unsigned)N || (unsigned)s >= (unsigned)N) return;
    g_csr[g_rowptr[d] + g_rank[e]] = s;
}

// ================= gathers =================
__global__ void gather128_kernel(const float* __restrict__ b1, int N) {
    int w    = (blockIdx.x * blockDim.x + threadIdx.x) >> 5;
    int lane = threadIdx.x & 31;
    if (w >= N) return;
    int beg = g_rowptr[w], end = g_rowptr[w + 1];
    float4 acc = make_float4(0.f, 0.f, 0.f, 0.f);
    for (int e = beg; e < end; e++) {
        int s    = g_csr[e];
        float ws = g_dinv[s];
        float4 v = *(const float4*)(g_h1 + (size_t)s * 128 + lane * 4);
        acc.x += ws * v.x; acc.y += ws * v.y; acc.z += ws * v.z; acc.w += ws * v.w;
    }
    float dd = g_dinv[w];
    float d2 = dd * dd;
    float4 self = *(const float4*)(g_h1 + (size_t)w * 128 + lane * 4);
    float4 bv   = *(const float4*)(b1 + lane * 4);
    float4 r;
    r.x = fmaxf(dd * acc.x + d2 * self.x + bv.x, 0.f);
    r.y = fmaxf(dd * acc.y + d2 * self.y + bv.y, 0.f);
    r.z = fmaxf(dd * acc.z + d2 * self.z + bv.z, 0.f);
    r.w = fmaxf(dd * acc.w + d2 * self.w + bv.w, 0.f);
    *(float4*)(g_hrelu + (size_t)w * 128 + lane * 4) = r;
}
__global__ void gather64_kernel(const float* __restrict__ b2, float* __restrict__ out, int N) {
    int w    = (blockIdx.x * blockDim.x + threadIdx.x) >> 5;
    int lane = threadIdx.x & 31;
    if (w >= N) return;
    int beg = g_rowptr[w], end = g_rowptr[w + 1];
    float2 acc = make_float2(0.f, 0.f);
    for (int e = beg; e < end; e++) {
        int s    = g_csr[e];
        float ws = g_dinv[s];
        float2 v = *(const float2*)(g_h2 + (size_t)s * 64 + lane * 2);
        acc.x += ws * v.x; acc.y += ws * v.y;
    }
    float dd = g_dinv[w];
    float d2 = dd * dd;
    float2 self = *(const float2*)(g_h2 + (size_t)w * 64 + lane * 2);
    float2 bv   = *(const float2*)(b2 + lane * 2);
    float2 r;
    r.x = dd * acc.x + d2 * self.x + bv.x;
    r.y = dd * acc.y + d2 * self.y + bv.y;
    *(float2*)(out + (size_t)w * 64 + lane * 2) = r;
}

// ================= launch =================
extern "C" void kernel_launch(void* const* d_in, const int* in_sizes, int n_in,
                              void* d_out, int out_size) {
    const float* x  = (const float*)d_in[0];
    const int*   ei = (const int*)d_in[1];     // int32 (JAX x64 disabled)
    const float* W1 = (const float*)d_in[2];
    const float* b1 = (const float*)d_in[3];
    const float* W2 = (const float*)d_in[4];
    const float* b2 = (const float*)d_in[5];
    float* out = (float*)d_out;

    int N = in_sizes[0] / 128;
    int E = in_sizes[1] / 2;
    if (N > N_MAX) N = N_MAX;
    if (E > E_MAX) E = E_MAX;

    const int TPB = 256;

    constexpr int SMEM1 = (128 + 128) * 36 * 8;   // 73728 B -> 2 CTAs/SM
    constexpr int SMEM2 = (128 + 64)  * 36 * 8;   // 55296 B -> 2 CTAs/SM (reg-capped)
    cudaFuncSetAttribute(gemm1_kernel, cudaFuncAttributeMaxDynamicSharedMemorySize, SMEM1);
    cudaFuncSetAttribute(gemm2_kernel, cudaFuncAttributeMaxDynamicSharedMemorySize, SMEM2);

    int tiles = (N + 127) / 128;

    // order keeps gemm1 at my launch index 3 (the ncu-profiled slot)
    zero_count_kernel<<<(N + TPB - 1) / TPB, TPB>>>(N);                    // 0
    degree_kernel<<<(E + TPB - 1) / TPB, TPB>>>(ei, E, N);                 // 1
    wsplit_kernel<<<(128 * 128 + TPB - 1) / TPB, TPB>>>(W1, 128, 0);       // 2
    gemm1_kernel<<<tiles, 256, SMEM1>>>(x, N);                             // 3 <- profiled
    scan_kernel<<<1, 1024>>>(N);                                           // 4
    fill_csr_kernel<<<(E + TPB - 1) / TPB, TPB>>>(ei, E, N);               // 5
    {
        long long tot = (long long)N * 32;
        gather128_kernel<<<(int)((tot + TPB - 1) / TPB), TPB>>>(b1, N);    // 6
    }
    wsplit_kernel<<<(128 * 64 + TPB - 1) / TPB, TPB>>>(W2, 64, 1);         // 7
    gemm2_kernel<<<tiles, 256, SMEM2>>>(N);                                // 8
    {
        long long tot = (long long)N * 32;
        gather64_kernel<<<(int)((tot + TPB - 1) / TPB), TPB>>>(b2, out, N); // 9
    }
}

// round 13
// speedup vs baseline: 1.1693x; 1.1380x over previous
#include <cuda_runtime.h>
#include <cuda_bf16.h>
#include <cstdint>

#define N_MAX 50000
#define E_MAX 800000

// ---------------- scratch (device globals) ----------------
__device__ int   g_count [N_MAX];
__device__ int   g_rowptr[N_MAX + 1];
__device__ int   g_rank  [E_MAX];
__device__ int   g_csr   [E_MAX];
__device__ float g_dinv  [N_MAX];
__device__ float g_h1    [(size_t)N_MAX * 128];
__device__ float g_hrelu [(size_t)N_MAX * 128];
__device__ float g_h2    [(size_t)N_MAX * 64];
// W pre-split bf16 planes, layout [n][k] (k contiguous)
__device__ unsigned short g_W1hi[128 * 128];
__device__ unsigned short g_W1lo[128 * 128];
__device__ unsigned short g_W2hi[64 * 128];
__device__ unsigned short g_W2lo[64 * 128];

// ---------------- bf16 helpers ----------------
__device__ __forceinline__ void bf16_split(float x, unsigned short& hi, unsigned short& lo) {
    __nv_bfloat16 h = __float2bfloat16(x);
    float r = x - __bfloat162float(h);
    __nv_bfloat16 l = __float2bfloat16(r);
    hi = *reinterpret_cast<unsigned short*>(&h);
    lo = *reinterpret_cast<unsigned short*>(&l);
}
__device__ __forceinline__ void mma_bf16(float* c, const uint32_t* a, const uint32_t* b) {
    asm volatile(
        "mma.sync.aligned.m16n8k16.row.col.f32.bf16.bf16.f32 "
        "{%0,%1,%2,%3}, {%4,%5,%6,%7}, {%8,%9}, {%0,%1,%2,%3};"
        : "+f"(c[0]), "+f"(c[1]), "+f"(c[2]), "+f"(c[3])
        : "r"(a[0]), "r"(a[1]), "r"(a[2]), "r"(a[3]), "r"(b[0]), "r"(b[1]));
}

// ---------------- W transpose + split (destination chosen in DEVICE code) ----------------
__global__ void wsplit_kernel(const float* __restrict__ W, int BN, int which) {
    int idx = blockIdx.x * blockDim.x + threadIdx.x;   // over 128*BN
    if (idx >= 128 * BN) return;
    int k = idx / BN, n = idx % BN;
    unsigned short hi, lo;
    bf16_split(W[idx], hi, lo);
    unsigned short* Whi = which ? g_W2hi : g_W1hi;
    unsigned short* Wlo = which ? g_W2lo : g_W1lo;
    Whi[n * 128 + k] = hi;
    Wlo[n * 128 + k] = lo;
}

// ================= GEMM: C[N,BN] = A[N,128] @ W[128,BN] =================
// 256 threads = 8 warps (4 M x 2 N). BM=128. K in 2 halves of 64.
// bf16 m16n8k16, 3-term split: Ahi*Bhi + Ahi*Blo + Alo*Bhi (fp32 accum).
// Smem: hi/lo bf16 planes, row stride 72 (36 words == 4 mod 32 -> conflict-free
// for the (4*grp + tig) fragment access pattern).
template<int BN>
__device__ __forceinline__ void gemm_mma_body(const float* __restrict__ A,
                                              const unsigned short* __restrict__ Whi,
                                              const unsigned short* __restrict__ Wlo,
                                              float* __restrict__ C, int N) {
    constexpr int NT   = BN / 16;   // n8 tiles per warp
    constexpr int LDKB = 72;        // bf16 per row (64 + 8 pad)
    extern __shared__ unsigned short sus[];
    unsigned short* As_hi = sus;                    // [128][72]
    unsigned short* As_lo = sus + 128 * LDKB;
    unsigned short* Ws_hi = sus + 2 * 128 * LDKB;   // [BN][72]
    unsigned short* Ws_lo = Ws_hi + BN * LDKB;

    int tid  = threadIdx.x;
    int lane = tid & 31, wid = tid >> 5;
    int warpM = wid & 3, warpN = wid >> 2;
    int grp = lane >> 2, tig = lane & 3;
    int rowBase = blockIdx.x * 128;

    float acc[2][NT][4];
#pragma unroll
    for (int mt = 0; mt < 2; mt++)
#pragma unroll
        for (int nt = 0; nt < NT; nt++)
#pragma unroll
            for (int i = 0; i < 4; i++) acc[mt][nt][i] = 0.f;

#pragma unroll
    for (int h = 0; h < 2; h++) {
        // ---- stage A half (128 x 64 fp32 -> hi/lo bf16 planes) ----
#pragma unroll
        for (int it = 0; it < 8; it++) {
            int idx = tid + it * 256;        // 2048 float4 over 128x16
            int r = idx >> 4, c4 = idx & 15;
            float4 v = make_float4(0.f, 0.f, 0.f, 0.f);
            int gr = rowBase + r;
            if (gr < N) v = *(const float4*)(A + (size_t)gr * 128 + h * 64 + c4 * 4);
            unsigned short h0, h1, h2, h3, l0, l1, l2, l3;
            bf16_split(v.x, h0, l0); bf16_split(v.y, h1, l1);
            bf16_split(v.z, h2, l2); bf16_split(v.w, h3, l3);
            int off = r * LDKB + c4 * 4;
            *(uint2*)(As_hi + off) = make_uint2((uint32_t)h0 | ((uint32_t)h1 << 16),
                                                (uint32_t)h2 | ((uint32_t)h3 << 16));
            *(uint2*)(As_lo + off) = make_uint2((uint32_t)l0 | ((uint32_t)l1 << 16),
                                                (uint32_t)l2 | ((uint32_t)l3 << 16));
        }
        // ---- stage W half: coalesced copy from pre-split planes ----
#pragma unroll
        for (int it = 0; it < BN / 32; it++) {
            int idx = tid + it * 256;        // BN*8 uint4 per plane
            int n = idx >> 3, q = idx & 7;
            uint4 vh = *(const uint4*)(Whi + (size_t)n * 128 + h * 64 + q * 8);
            uint4 vl = *(const uint4*)(Wlo + (size_t)n * 128 + h * 64 + q * 8);
            *(uint4*)(Ws_hi + n * LDKB + q * 8) = vh;
            *(uint4*)(Ws_lo + n * LDKB + q * 8) = vl;
        }
        __syncthreads();

#pragma unroll
        for (int kt = 0; kt < 4; kt++) {
            int k0 = kt * 16;
            int ka = k0 + 2 * tig;
            uint32_t ah[2][4], al[2][4];
#pragma unroll
            for (int mt = 0; mt < 2; mt++) {
                int r = warpM * 32 + mt * 16 + grp;
                ah[mt][0] = *(const uint32_t*)(As_hi + r       * LDKB + ka);
                ah[mt][1] = *(const uint32_t*)(As_hi + (r + 8) * LDKB + ka);
                ah[mt][2] = *(const uint32_t*)(As_hi + r       * LDKB + ka + 8);
                ah[mt][3] = *(const uint32_t*)(As_hi + (r + 8) * LDKB + ka + 8);
                al[mt][0] = *(const uint32_t*)(As_lo + r       * LDKB + ka);
                al[mt][1] = *(const uint32_t*)(As_lo + (r + 8) * LDKB + ka);
                al[mt][2] = *(const uint32_t*)(As_lo + r       * LDKB + ka + 8);
                al[mt][3] = *(const uint32_t*)(As_lo + (r + 8) * LDKB + ka + 8);
            }
            uint32_t bh[NT][2], bl[NT][2];
#pragma unroll
            for (int nt = 0; nt < NT; nt++) {
                int n = warpN * (BN / 2) + nt * 8 + grp;
                bh[nt][0] = *(const uint32_t*)(Ws_hi + n * LDKB + ka);
                bh[nt][1] = *(const uint32_t*)(Ws_hi + n * LDKB + ka + 8);
                bl[nt][0] = *(const uint32_t*)(Ws_lo + n * LDKB + ka);
                bl[nt][1] = *(const uint32_t*)(Ws_lo + n * LDKB + ka + 8);
            }
#pragma unroll
            for (int mt = 0; mt < 2; mt++)
#pragma unroll
                for (int nt = 0; nt < NT; nt++) {
                    mma_bf16(acc[mt][nt], ah[mt], bh[nt]);
                    mma_bf16(acc[mt][nt], ah[mt], bl[nt]);
                    mma_bf16(acc[mt][nt], al[mt], bh[nt]);
                }
        }
        __syncthreads();
    }

    // ---- store C ----
#pragma unroll
    for (int mt = 0; mt < 2; mt++) {
        int r0 = rowBase + warpM * 32 + mt * 16 + grp;
#pragma unroll
        for (int nt = 0; nt < NT; nt++) {
            int c = warpN * (BN / 2) + nt * 8 + tig * 2;
            if (r0 < N)
                *(float2*)(C + (size_t)r0 * BN + c) = make_float2(acc[mt][nt][0], acc[mt][nt][1]);
            if (r0 + 8 < N)
                *(float2*)(C + (size_t)(r0 + 8) * BN + c) = make_float2(acc[mt][nt][2], acc[mt][nt][3]);
        }
    }
}

__global__ __launch_bounds__(256, 2) void gemm1_kernel(const float* __restrict__ A, int N) {
    gemm_mma_body<128>(A, g_W1hi, g_W1lo, g_h1, N);
}
__global__ __launch_bounds__(256, 2) void gemm2_kernel(int N) {
    gemm_mma_body<64>(g_hrelu, g_W2hi, g_W2lo, g_h2, N);
}

// ================= CSR build =================
__global__ void zero_count_kernel(int N) {
    int i = blockIdx.x * blockDim.x + threadIdx.x;
    if (i < N) g_count[i] = 0;
}
__global__ void degree_kernel(const int* __restrict__ ei, int E, int N) {
    int e = blockIdx.x * blockDim.x + threadIdx.x;
    if (e >= E) return;
    int d = ei[E + e];
    int p = 0;
    if ((unsigned)d < (unsigned)N) p = atomicAdd(&g_count[d], 1);
    g_rank[e] = p;
}
__global__ void scan_kernel(int N) {
    __shared__ int sh[1024];
    int tid = threadIdx.x;
    int chunk = (N + 1023) >> 10;
    int start = tid * chunk;
    int end   = min(start + chunk, N);
    int s = 0;
    for (int i = start; i < end; i++) s += g_count[i];
    sh[tid] = s;
    __syncthreads();
    for (int off = 1; off < 1024; off <<= 1) {
        int v = 0;
        if (tid >= off) v = sh[tid - off];
        __syncthreads();
        if (tid >= off) sh[tid] += v;
        __syncthreads();
    }
    int offset = (tid == 0) ? 0 : sh[tid - 1];
    for (int i = start; i < end; i++) {
        g_rowptr[i] = offset;
        offset += g_count[i];
        g_dinv[i] = rsqrtf((float)g_count[i] + 1.0f);
    }
    if (end == N && start <= N) g_rowptr[N] = offset;
}
__global__ void fill_csr_kernel(const int* __restrict__ ei, int E, int N) {
    int e = blockIdx.x * blockDim.x + threadIdx.x;
    if (e >= E) return;
    int s = ei[e];
    int d = ei[E + e];
    if ((unsigned)d >= (unsigned)N || (unsigned)s >= (unsigned)N) return;
    g_csr[g_rowptr[d] + g_rank[e]] = s;
}

// ================= gathers (edge loop unrolled x2 for MLP) =================
__global__ void gather128_kernel(const float* __restrict__ b1, int N) {
    int w    = (blockIdx.x * blockDim.x + threadIdx.x) >> 5;
    int lane = threadIdx.x & 31;
    if (w >= N) return;
    int beg = g_rowptr[w], end = g_rowptr[w + 1];
    float4 acc = make_float4(0.f, 0.f, 0.f, 0.f);
    int e = beg;
    for (; e + 1 < end; e += 2) {
        int s0 = g_csr[e], s1 = g_csr[e + 1];
        float w0 = g_dinv[s0], w1 = g_dinv[s1];
        float4 v0 = *(const float4*)(g_h1 + (size_t)s0 * 128 + lane * 4);
        float4 v1 = *(const float4*)(g_h1 + (size_t)s1 * 128 + lane * 4);
        acc.x += w0 * v0.x + w1 * v1.x;
        acc.y += w0 * v0.y + w1 * v1.y;
        acc.z += w0 * v0.z + w1 * v1.z;
        acc.w += w0 * v0.w + w1 * v1.w;
    }
    if (e < end) {
        int s0 = g_csr[e];
        float w0 = g_dinv[s0];
        float4 v0 = *(const float4*)(g_h1 + (size_t)s0 * 128 + lane * 4);
        acc.x += w0 * v0.x; acc.y += w0 * v0.y; acc.z += w0 * v0.z; acc.w += w0 * v0.w;
    }
    float dd = g_dinv[w];
    float d2 = dd * dd;
    float4 self = *(const float4*)(g_h1 + (size_t)w * 128 + lane * 4);
    float4 bv   = *(const float4*)(b1 + lane * 4);
    float4 r;
    r.x = fmaxf(dd * acc.x + d2 * self.x + bv.x, 0.f);
    r.y = fmaxf(dd * acc.y + d2 * self.y + bv.y, 0.f);
    r.z = fmaxf(dd * acc.z + d2 * self.z + bv.z, 0.f);
    r.w = fmaxf(dd * acc.w + d2 * self.w + bv.w, 0.f);
    *(float4*)(g_hrelu + (size_t)w * 128 + lane * 4) = r;
}
__global__ void gather64_kernel(const float* __restrict__ b2, float* __restrict__ out, int N) {
    int w    = (blockIdx.x * blockDim.x + threadIdx.x) >> 5;
    int lane = threadIdx.x & 31;
    if (w >= N) return;
    int beg = g_rowptr[w], end = g_rowptr[w + 1];
    float2 acc = make_float2(0.f, 0.f);
    int e = beg;
    for (; e + 1 < end; e += 2) {
        int s0 = g_csr[e], s1 = g_csr[e + 1];
        float w0 = g_dinv[s0], w1 = g_dinv[s1];
        float2 v0 = *(const float2*)(g_h2 + (size_t)s0 * 64 + lane * 2);
        float2 v1 = *(const float2*)(g_h2 + (size_t)s1 * 64 + lane * 2);
        acc.x += w0 * v0.x + w1 * v1.x;
        acc.y += w0 * v0.y + w1 * v1.y;
    }
    if (e < end) {
        int s0 = g_csr[e];
        float w0 = g_dinv[s0];
        float2 v0 = *(const float2*)(g_h2 + (size_t)s0 * 64 + lane * 2);
        acc.x += w0 * v0.x; acc.y += w0 * v0.y;
    }
    float dd = g_dinv[w];
    float d2 = dd * dd;
    float2 self = *(const float2*)(g_h2 + (size_t)w * 64 + lane * 2);
    float2 bv   = *(const float2*)(b2 + lane * 2);
    float2 r;
    r.x = dd * acc.x + d2 * self.x + bv.x;
    r.y = dd * acc.y + d2 * self.y + bv.y;
    *(float2*)(out + (size_t)w * 64 + lane * 2) = r;
}

// ================= launch =================
extern "C" void kernel_launch(void* const* d_in, const int* in_sizes, int n_in,
                              void* d_out, int out_size) {
    const float* x  = (const float*)d_in[0];
    const int*   ei = (const int*)d_in[1];     // int32 (JAX x64 disabled)
    const float* W1 = (const float*)d_in[2];
    const float* b1 = (const float*)d_in[3];
    const float* W2 = (const float*)d_in[4];
    const float* b2 = (const float*)d_in[5];
    float* out = (float*)d_out;

    int N = in_sizes[0] / 128;
    int E = in_sizes[1] / 2;
    if (N > N_MAX) N = N_MAX;
    if (E > E_MAX) E = E_MAX;

    const int TPB = 256;

    constexpr int SMEM1 = (2 * 128 + 2 * 128) * 72 * 2;   // 73728 B -> 2 CTAs/SM
    constexpr int SMEM2 = (2 * 128 + 2 * 64)  * 72 * 2;   // 55296 B -> 2 CTAs/SM
    cudaFuncSetAttribute(gemm1_kernel, cudaFuncAttributeMaxDynamicSharedMemorySize, SMEM1);
    cudaFuncSetAttribute(gemm2_kernel, cudaFuncAttributeMaxDynamicSharedMemorySize, SMEM2);

    int tiles = (N + 127) / 128;

    // order keeps gemm1 at my launch index 3 (the ncu-profiled slot)
    zero_count_kernel<<<(N + TPB - 1) / TPB, TPB>>>(N);                    // 0
    degree_kernel<<<(E + TPB - 1) / TPB, TPB>>>(ei, E, N);                 // 1
    wsplit_kernel<<<(128 * 128 + TPB - 1) / TPB, TPB>>>(W1, 128, 0);       // 2
    gemm1_kernel<<<tiles, 256, SMEM1>>>(x, N);                             // 3 <- profiled
    scan_kernel<<<1, 1024>>>(N);                                           // 4
    fill_csr_kernel<<<(E + TPB - 1) / TPB, TPB>>>(ei, E, N);               // 5
    {
        long long tot = (long long)N * 32;
        gather128_kernel<<<(int)((tot + TPB - 1) / TPB), TPB>>>(b1, N);    // 6
    }
    wsplit_kernel<<<(128 * 64 + TPB - 1) / TPB, TPB>>>(W2, 64, 1);         // 7
    gemm2_kernel<<<tiles, 256, SMEM2>>>(N);                                // 8
    {
        long long tot = (long long)N * 32;
        gather64_kernel<<<(int)((tot + TPB - 1) / TPB), TPB>>>(b2, out, N); // 9
    }
}

// round 14
// speedup vs baseline: 1.6555x; 1.4158x over previous
#include <cuda_runtime.h>
#include <cuda_bf16.h>
#include <cstdint>

#define N_MAX 50000
#define E_MAX 800000

// ---------------- scratch (device globals; referenced ONLY in device code) ----------
__device__ int   g_count [N_MAX];
__device__ int   g_rowptr[N_MAX + 1];
__device__ int   g_rank  [E_MAX];
__device__ int   g_csr   [E_MAX];
__device__ int   g_bsum  [256];
__device__ int   g_boff  [256];
__device__ float g_dinv  [N_MAX];
__device__ float g_h1    [(size_t)N_MAX * 128];
__device__ float g_h2    [(size_t)N_MAX * 64];
// bf16 hi/lo planes, [row][k] (k contiguous)
__device__ unsigned short g_Xhi[(size_t)N_MAX * 128];
__device__ unsigned short g_Xlo[(size_t)N_MAX * 128];
__device__ unsigned short g_Hhi[(size_t)N_MAX * 128];
__device__ unsigned short g_Hlo[(size_t)N_MAX * 128];
__device__ unsigned short g_W1hi[128 * 128];
__device__ unsigned short g_W1lo[128 * 128];
__device__ unsigned short g_W2hi[64 * 128];
__device__ unsigned short g_W2lo[64 * 128];

// ---------------- helpers ----------------
__device__ __forceinline__ uint32_t smem_u32(const void* p) {
    uint32_t a;
    asm("{ .reg .u64 t; cvta.to.shared.u64 t, %1; cvt.u32.u64 %0, t; }" : "=r"(a) : "l"(p));
    return a;
}
__device__ __forceinline__ void bf16_split(float x, unsigned short& hi, unsigned short& lo) {
    __nv_bfloat16 h = __float2bfloat16(x);
    float r = x - __bfloat162float(h);
    __nv_bfloat16 l = __float2bfloat16(r);
    hi = *reinterpret_cast<unsigned short*>(&h);
    lo = *reinterpret_cast<unsigned short*>(&l);
}
__device__ __forceinline__ void mma_bf16(float* c, const uint32_t* a, const uint32_t* b) {
    asm volatile(
        "mma.sync.aligned.m16n8k16.row.col.f32.bf16.bf16.f32 "
        "{%0,%1,%2,%3}, {%4,%5,%6,%7}, {%8,%9}, {%0,%1,%2,%3};"
        : "+f"(c[0]), "+f"(c[1]), "+f"(c[2]), "+f"(c[3])
        : "r"(a[0]), "r"(a[1]), "r"(a[2]), "r"(a[3]), "r"(b[0]), "r"(b[1]));
}
#define CP_ASYNC16(dst, src, sz) \
    asm volatile("cp.async.cg.shared.global [%0], [%1], 16, %2;" \
                 :: "r"(dst), "l"(src), "r"(sz) : "memory")
#define CP_COMMIT  asm volatile("cp.async.commit_group;" ::: "memory")
#define CP_WAIT0   asm volatile("cp.async.wait_group 0;" ::: "memory")
#define CP_WAIT1   asm volatile("cp.async.wait_group 1;" ::: "memory")

// ---------------- x -> bf16 hi/lo planes ----------------
__global__ void xsplit_kernel(const float* __restrict__ x, int total4) {
    int i = blockIdx.x * blockDim.x + threadIdx.x;     // over N*32 float4
    if (i >= total4) return;
    float4 v = ((const float4*)x)[i];
    unsigned short h0, h1, h2, h3, l0, l1, l2, l3;
    bf16_split(v.x, h0, l0); bf16_split(v.y, h1, l1);
    bf16_split(v.z, h2, l2); bf16_split(v.w, h3, l3);
    *(uint2*)(g_Xhi + (size_t)i * 4) = make_uint2((uint32_t)h0 | ((uint32_t)h1 << 16),
                                                  (uint32_t)h2 | ((uint32_t)h3 << 16));
    *(uint2*)(g_Xlo + (size_t)i * 4) = make_uint2((uint32_t)l0 | ((uint32_t)l1 << 16),
                                                  (uint32_t)l2 | ((uint32_t)l3 << 16));
}

// ---------------- W transpose + split (destination chosen in DEVICE code) ----------------
__global__ void wsplit_kernel(const float* __restrict__ W, int BN, int which) {
    int idx = blockIdx.x * blockDim.x + threadIdx.x;   // over 128*BN
    if (idx >= 128 * BN) return;
    int k = idx / BN, n = idx % BN;
    unsigned short hi, lo;
    bf16_split(W[idx], hi, lo);
    unsigned short* Whi = which ? g_W2hi : g_W1hi;
    unsigned short* Wlo = which ? g_W2lo : g_W1lo;
    Whi[n * 128 + k] = hi;
    Wlo[n * 128 + k] = lo;
}

// ================= persistent pipelined GEMM: C[N,BN] = A[N,128] @ W[128,BN] ==========
// 256 thr = 8 warps (4M x 2N), BM=128. W planes staged ONCE (full K, LDW=136 shorts,
// 68 words == 4 mod 32 -> conflict-free frags). A streamed as 4 K-chunks of 32 via
// depth-2 cp.async pipeline (LDA=40 shorts, 20 words == 20 mod 32 -> conflict-free).
// bf16 m16n8k16, 3-term split: Ahi*Bhi + Ahi*Blo + Alo*Bhi.
template<int BN>
__device__ __forceinline__ void gemm_body(const unsigned short* __restrict__ Ahi,
                                          const unsigned short* __restrict__ Alo,
                                          const unsigned short* __restrict__ Whi,
                                          const unsigned short* __restrict__ Wlo,
                                          float* __restrict__ C, int N, int tiles) {
    constexpr int NT     = BN / 16;
    constexpr int LDW    = 136;           // shorts per W row (128 + 8 pad)
    constexpr int LDA    = 40;            // shorts per A row per chunk (32 + 8 pad)
    constexpr int APLANE = 128 * LDA;
    extern __shared__ unsigned short sus[];
    unsigned short* sW = sus;                     // [2 planes][BN][LDW]
    unsigned short* sA = sus + 2 * BN * LDW;      // [2 buf][2 planes][128][LDA]
    uint32_t sW_addr = smem_u32(sW);
    uint32_t sA_addr = smem_u32(sA);

    int tid  = threadIdx.x;
    int lane = tid & 31, wid = tid >> 5;
    int warpM = wid & 3, warpN = wid >> 2;
    int grp = lane >> 2, tig = lane & 3;

    // ---- stage W once (both planes, full K) ----
#pragma unroll
    for (int it = 0; it < BN / 8; it++) {
        int idx = tid + it * 256;                  // 2*BN*16 chunks of 16B
        int plane = idx / (BN * 16);
        int rem   = idx - plane * (BN * 16);
        int n = rem >> 4, c = rem & 15;
        const unsigned short* src = (plane ? Wlo : Whi) + n * 128 + c * 8;
        uint32_t dst = sW_addr + (uint32_t)(((plane * BN + n) * LDW + c * 8) * 2);
        CP_ASYNC16(dst, src, 16);
    }

    for (int tile = blockIdx.x; tile < tiles; tile += gridDim.x) {
        int rowBase = tile * 128;
        // issue A chunk 0 into buf 0 (first tile's group also carries W)
        {
#pragma unroll
            for (int it = 0; it < 4; it++) {
                int idx = tid + it * 256;
                int plane = idx >> 9, rem = idx & 511;
                int r = rem >> 2, c = rem & 3;
                int gr = rowBase + r;
                const unsigned short* src = (plane ? Alo : Ahi) + (size_t)gr * 128 + c * 8;
                uint32_t dst = sA_addr + (uint32_t)((((0 * 2 + plane) * 128 + r) * LDA + c * 8) * 2);
                CP_ASYNC16(dst, src, gr < N ? 16 : 0);
            }
            CP_COMMIT;
        }

        float acc[2][NT][4];
#pragma unroll
        for (int mt = 0; mt < 2; mt++)
#pragma unroll
            for (int nt = 0; nt < NT; nt++)
#pragma unroll
                for (int i = 0; i < 4; i++) acc[mt][nt][i] = 0.f;

        int buf = 0;
#pragma unroll
        for (int ch = 0; ch < 4; ch++) {
            if (ch < 3) {
#pragma unroll
                for (int it = 0; it < 4; it++) {
                    int idx = tid + it * 256;
                    int plane = idx >> 9, rem = idx & 511;
                    int r = rem >> 2, c = rem & 3;
                    int gr = rowBase + r;
                    const unsigned short* src =
                        (plane ? Alo : Ahi) + (size_t)gr * 128 + (ch + 1) * 32 + c * 8;
                    uint32_t dst = sA_addr +
                        (uint32_t)(((((buf ^ 1) * 2 + plane) * 128 + r) * LDA + c * 8) * 2);
                    CP_ASYNC16(dst, src, gr < N ? 16 : 0);
                }
                CP_COMMIT;
                CP_WAIT1;
            } else {
                CP_WAIT0;
            }
            __syncthreads();

            const unsigned short* Ah = sA + (buf * 2 + 0) * APLANE;
            const unsigned short* Al = sA + (buf * 2 + 1) * APLANE;
#pragma unroll
            for (int kt = 0; kt < 2; kt++) {
                int ka = kt * 16 + 2 * tig;
                int kw = ch * 32 + ka;
                uint32_t ah[2][4], al[2][4];
#pragma unroll
                for (int mt = 0; mt < 2; mt++) {
                    int r = warpM * 32 + mt * 16 + grp;
                    ah[mt][0] = *(const uint32_t*)(Ah + r       * LDA + ka);
                    ah[mt][1] = *(const uint32_t*)(Ah + (r + 8) * LDA + ka);
                    ah[mt][2] = *(const uint32_t*)(Ah + r       * LDA + ka + 8);
                    ah[mt][3] = *(const uint32_t*)(Ah + (r + 8) * LDA + ka + 8);
                    al[mt][0] = *(const uint32_t*)(Al + r       * LDA + ka);
                    al[mt][1] = *(const uint32_t*)(Al + (r + 8) * LDA + ka);
                    al[mt][2] = *(const uint32_t*)(Al + r       * LDA + ka + 8);
                    al[mt][3] = *(const uint32_t*)(Al + (r + 8) * LDA + ka + 8);
                }
                uint32_t bh[NT][2], bl[NT][2];
#pragma unroll
                for (int nt = 0; nt < NT; nt++) {
                    int n = warpN * (BN / 2) + nt * 8 + grp;
                    bh[nt][0] = *(const uint32_t*)(sW + n * LDW + kw);
                    bh[nt][1] = *(const uint32_t*)(sW + n * LDW + kw + 8);
                    bl[nt][0] = *(const uint32_t*)(sW + (BN + n) * LDW + kw);
                    bl[nt][1] = *(const uint32_t*)(sW + (BN + n) * LDW + kw + 8);
                }
#pragma unroll
                for (int mt = 0; mt < 2; mt++)
#pragma unroll
                    for (int nt = 0; nt < NT; nt++) {
                        mma_bf16(acc[mt][nt], ah[mt], bh[nt]);
                        mma_bf16(acc[mt][nt], ah[mt], bl[nt]);
                        mma_bf16(acc[mt][nt], al[mt], bh[nt]);
                    }
            }
            __syncthreads();
            buf ^= 1;
        }

        // ---- store C ----
#pragma unroll
        for (int mt = 0; mt < 2; mt++) {
            int r0 = rowBase + warpM * 32 + mt * 16 + grp;
#pragma unroll
            for (int nt = 0; nt < NT; nt++) {
                int c = warpN * (BN / 2) + nt * 8 + tig * 2;
                if (r0 < N)
                    *(float2*)(C + (size_t)r0 * BN + c) = make_float2(acc[mt][nt][0], acc[mt][nt][1]);
                if (r0 + 8 < N)
                    *(float2*)(C + (size_t)(r0 + 8) * BN + c) = make_float2(acc[mt][nt][2], acc[mt][nt][3]);
            }
        }
    }
    CP_WAIT0;   // drain (covers CTAs that issued W but got no tile)
}

__global__ __launch_bounds__(256, 2) void gemm1_kernel(int N, int tiles) {
    gemm_body<128>(g_Xhi, g_Xlo, g_W1hi, g_W1lo, g_h1, N, tiles);
}
__global__ __launch_bounds__(256, 2) void gemm2_kernel(int N, int tiles) {
    gemm_body<64>(g_Hhi, g_Hlo, g_W2hi, g_W2lo, g_h2, N, tiles);
}

// ================= CSR build =================
__global__ void zero_count_kernel(int N) {
    int i = blockIdx.x * blockDim.x + threadIdx.x;
    if (i < N) g_count[i] = 0;
}
__global__ void degree_kernel(const int* __restrict__ ei, int E, int N) {
    int e = blockIdx.x * blockDim.x + threadIdx.x;
    if (e >= E) return;
    int d = ei[E + e];
    int p = 0;
    if ((unsigned)d < (unsigned)N) p = atomicAdd(&g_count[d], 1);
    g_rank[e] = p;
}
// 3-pass scan: partial sums -> block-offset scan -> final (fused dinv)
__global__ void scan_partial_kernel(int N) {
    __shared__ int sh[256];
    int t = threadIdx.x, b = blockIdx.x;
    int i = b * 256 + t;
    sh[t] = (i < N) ? g_count[i] : 0;
    __syncthreads();
    for (int off = 128; off > 0; off >>= 1) {
        if (t < off) sh[t] += sh[t + off];
        __syncthreads();
    }
    if (t == 0) g_bsum[b] = sh[0];
}
__global__ void scan_blocks_kernel(int nb) {
    __shared__ int sh[256];
    int t = threadIdx.x;
    int v = (t < nb) ? g_bsum[t] : 0;
    sh[t] = v;
    __syncthreads();
    for (int off = 1; off < 256; off <<= 1) {
        int a = 0;
        if (t >= off) a = sh[t - off];
        __syncthreads();
        if (t >= off) sh[t] += a;
        __syncthreads();
    }
    if (t < nb) g_boff[t] = sh[t] - v;     // exclusive prefix
}
__global__ void scan_final_kernel(int N) {
    __shared__ int sh[256];
    int t = threadIdx.x, b = blockIdx.x;
    int i = b * 256 + t;
    int c = (i < N) ? g_count[i] : 0;
    sh[t] = c;
    __syncthreads();
    for (int off = 1; off < 256; off <<= 1) {
        int a = 0;
        if (t >= off) a = sh[t - off];
        __syncthreads();
        if (t >= off) sh[t] += a;
        __syncthreads();
    }
    if (i < N) {
        int incl = sh[t] + g_boff[b];
        g_rowptr[i] = incl - c;
        g_dinv[i] = rsqrtf((float)c + 1.0f);
        if (i == N - 1) g_rowptr[N] = incl;
    }
}
__global__ void fill_csr_kernel(const int* __restrict__ ei, int E, int N) {
    int e = blockIdx.x * blockDim.x + threadIdx.x;
    if (e >= E) return;
    int s = ei[e];
    int d = ei[E + e];
    if ((unsigned)d >= (unsigned)N || (unsigned)s >= (unsigned)N) return;
    g_csr[g_rowptr[d] + g_rank[e]] = s;
}

// ================= gathers =================
// layer 1: reads fp32 h1, writes hrelu as bf16 hi/lo planes (gemm2's input format)
__global__ void gather128_kernel(const float* __restrict__ b1, int N) {
    int w    = (blockIdx.x * blockDim.x + threadIdx.x) >> 5;
    int lane = threadIdx.x & 31;
    if (w >= N) return;
    int beg = g_rowptr[w], end = g_rowptr[w + 1];
    float4 acc = make_float4(0.f, 0.f, 0.f, 0.f);
    int e = beg;
    for (; e + 1 < end; e += 2) {
        int s0 = g_csr[e], s1 = g_csr[e + 1];
        float w0 = g_dinv[s0], w1 = g_dinv[s1];
        float4 v0 = *(const float4*)(g_h1 + (size_t)s0 * 128 + lane * 4);
        float4 v1 = *(const float4*)(g_h1 + (size_t)s1 * 128 + lane * 4);
        acc.x += w0 * v0.x + w1 * v1.x;
        acc.y += w0 * v0.y + w1 * v1.y;
        acc.z += w0 * v0.z + w1 * v1.z;
        acc.w += w0 * v0.w + w1 * v1.w;
    }
    if (e < end) {
        int s0 = g_csr[e];
        float w0 = g_dinv[s0];
        float4 v0 = *(const float4*)(g_h1 + (size_t)s0 * 128 + lane * 4);
        acc.x += w0 * v0.x; acc.y += w0 * v0.y; acc.z += w0 * v0.z; acc.w += w0 * v0.w;
    }
    float dd = g_dinv[w];
    float d2 = dd * dd;
    float4 self = *(const float4*)(g_h1 + (size_t)w * 128 + lane * 4);
    float4 bv   = *(const float4*)(b1 + lane * 4);
    float4 r;
    r.x = fmaxf(dd * acc.x + d2 * self.x + bv.x, 0.f);
    r.y = fmaxf(dd * acc.y + d2 * self.y + bv.y, 0.f);
    r.z = fmaxf(dd * acc.z + d2 * self.z + bv.z, 0.f);
    r.w = fmaxf(dd * acc.w + d2 * self.w + bv.w, 0.f);
    unsigned short h0, h1v, h2v, h3, l0, l1v, l2v, l3;
    bf16_split(r.x, h0, l0); bf16_split(r.y, h1v, l1v);
    bf16_split(r.z, h2v, l2v); bf16_split(r.w, h3, l3);
    size_t off = (size_t)w * 128 + lane * 4;
    *(uint2*)(g_Hhi + off) = make_uint2((uint32_t)h0 | ((uint32_t)h1v << 16),
                                        (uint32_t)h2v | ((uint32_t)h3 << 16));
    *(uint2*)(g_Hlo + off) = make_uint2((uint32_t)l0 | ((uint32_t)l1v << 16),
                                        (uint32_t)l2v | ((uint32_t)l3 << 16));
}
__global__ void gather64_kernel(const float* __restrict__ b2, float* __restrict__ out, int N) {
    int w    = (blockIdx.x * blockDim.x + threadIdx.x) >> 5;
    int lane = threadIdx.x & 31;
    if (w >= N) return;
    int beg = g_rowptr[w], end = g_rowptr[w + 1];
    float2 acc = make_float2(0.f, 0.f);
    int e = beg;
    for (; e + 1 < end; e += 2) {
        int s0 = g_csr[e], s1 = g_csr[e + 1];
        float w0 = g_dinv[s0], w1 = g_dinv[s1];
        float2 v0 = *(const float2*)(g_h2 + (size_t)s0 * 64 + lane * 2);
        float2 v1 = *(const float2*)(g_h2 + (size_t)s1 * 64 + lane * 2);
        acc.x += w0 * v0.x + w1 * v1.x;
        acc.y += w0 * v0.y + w1 * v1.y;
    }
    if (e < end) {
        int s0 = g_csr[e];
        float w0 = g_dinv[s0];
        float2 v0 = *(const float2*)(g_h2 + (size_t)s0 * 64 + lane * 2);
        acc.x += w0 * v0.x; acc.y += w0 * v0.y;
    }
    float dd = g_dinv[w];
    float d2 = dd * dd;
    float2 self = *(const float2*)(g_h2 + (size_t)w * 64 + lane * 2);
    float2 bv   = *(const float2*)(b2 + lane * 2);
    float2 r;
    r.x = dd * acc.x + d2 * self.x + bv.x;
    r.y = dd * acc.y + d2 * self.y + bv.y;
    *(float2*)(out + (size_t)w * 64 + lane * 2) = r;
}

// ================= launch =================
extern "C" void kernel_launch(void* const* d_in, const int* in_sizes, int n_in,
                              void* d_out, int out_size) {
    const float* x  = (const float*)d_in[0];
    const int*   ei = (const int*)d_in[1];     // int32 (JAX x64 disabled)
    const float* W1 = (const float*)d_in[2];
    const float* b1 = (const float*)d_in[3];
    const float* W2 = (const float*)d_in[4];
    const float* b2 = (const float*)d_in[5];
    float* out = (float*)d_out;

    int N = in_sizes[0] / 128;
    int E = in_sizes[1] / 2;
    if (N > N_MAX) N = N_MAX;
    if (E > E_MAX) E = E_MAX;

    const int TPB = 256;
    int tiles = (N + 127) / 128;
    int nb    = (N + 255) / 256;

    constexpr int SMEM1 = (2 * 128 * 136 + 2 * 2 * 128 * 40) * 2;   // 110592 B -> 2 CTAs/SM
    constexpr int SMEM2 = (2 * 64  * 136 + 2 * 2 * 128 * 40) * 2;   //  75776 B -> 2 CTAs/SM
    cudaFuncSetAttribute(gemm1_kernel, cudaFuncAttributeMaxDynamicSharedMemorySize, SMEM1);
    cudaFuncSetAttribute(gemm2_kernel, cudaFuncAttributeMaxDynamicSharedMemorySize, SMEM2);

    // order keeps gemm1 at my launch index 3 (the ncu-profiled slot)
    zero_count_kernel<<<(N + TPB - 1) / TPB, TPB>>>(N);                      // 0
    xsplit_kernel<<<(N * 32 + TPB - 1) / TPB, TPB>>>(x, N * 32);             // 1
    wsplit_kernel<<<(128 * 128 + TPB - 1) / TPB, TPB>>>(W1, 128, 0);         // 2
    gemm1_kernel<<<296, 256, SMEM1>>>(N, tiles);                             // 3 <- profiled
    degree_kernel<<<(E + TPB - 1) / TPB, TPB>>>(ei, E, N);                   // 4
    scan_partial_kernel<<<nb, 256>>>(N);                                     // 5
    scan_blocks_kernel<<<1, 256>>>(nb);                                      // 6
    scan_final_kernel<<<nb, 256>>>(N);                                       // 7
    fill_csr_kernel<<<(E + TPB - 1) / TPB, TPB>>>(ei, E, N);                 // 8
    {
        long long tot = (long long)N * 32;
        gather128_kernel<<<(int)((tot + TPB - 1) / TPB), TPB>>>(b1, N);      // 9
    }
    wsplit_kernel<<<(128 * 64 + TPB - 1) / TPB, TPB>>>(W2, 64, 1);           // 10
    gemm2_kernel<<<296, 256, SMEM2>>>(N, tiles);                             // 11
    {
        long long tot = (long long)N * 32;
        gather64_kernel<<<(int)((tot + TPB - 1) / TPB), TPB>>>(b2, out, N);  // 12
    }
}

// round 15
// speedup vs baseline: 1.9288x; 1.1651x over previous
#include <cuda_runtime.h>
#include <cuda_bf16.h>
#include <cstdint>

#define N_MAX 50000
#define E_MAX 800000

// ---------------- scratch (device globals; referenced ONLY in device code) ----------
__device__ int   g_count [N_MAX];
__device__ int   g_rowptr[N_MAX + 1];
__device__ int   g_rank  [E_MAX];
__device__ int   g_csr   [E_MAX];
__device__ int   g_bsum  [256];
__device__ int   g_boff  [256];
__device__ float g_dinv  [N_MAX];
__device__ float g_h1    [(size_t)N_MAX * 128];
__device__ float g_h2    [(size_t)N_MAX * 64];
// bf16 hi/lo planes, [row][k] (k contiguous)
__device__ unsigned short g_Xhi[(size_t)N_MAX * 128];
__device__ unsigned short g_Xlo[(size_t)N_MAX * 128];
__device__ unsigned short g_Hhi[(size_t)N_MAX * 128];
__device__ unsigned short g_Hlo[(size_t)N_MAX * 128];
__device__ unsigned short g_W1hi[128 * 128];
__device__ unsigned short g_W1lo[128 * 128];
__device__ unsigned short g_W2hi[64 * 128];
__device__ unsigned short g_W2lo[64 * 128];

// ---------------- helpers ----------------
__device__ __forceinline__ uint32_t smem_u32(const void* p) {
    uint32_t a;
    asm("{ .reg .u64 t; cvta.to.shared.u64 t, %1; cvt.u32.u64 %0, t; }" : "=r"(a) : "l"(p));
    return a;
}
__device__ __forceinline__ void bf16_split(float x, unsigned short& hi, unsigned short& lo) {
    __nv_bfloat16 h = __float2bfloat16(x);
    float r = x - __bfloat162float(h);
    __nv_bfloat16 l = __float2bfloat16(r);
    hi = *reinterpret_cast<unsigned short*>(&h);
    lo = *reinterpret_cast<unsigned short*>(&l);
}
__device__ __forceinline__ void mma_bf16(float* c, const uint32_t* a, const uint32_t* b) {
    asm volatile(
        "mma.sync.aligned.m16n8k16.row.col.f32.bf16.bf16.f32 "
        "{%0,%1,%2,%3}, {%4,%5,%6,%7}, {%8,%9}, {%0,%1,%2,%3};"
        : "+f"(c[0]), "+f"(c[1]), "+f"(c[2]), "+f"(c[3])
        : "r"(a[0]), "r"(a[1]), "r"(a[2]), "r"(a[3]), "r"(b[0]), "r"(b[1]));
}
#define CP_ASYNC16(dst, src, sz) \
    asm volatile("cp.async.cg.shared.global [%0], [%1], 16, %2;" \
                 :: "r"(dst), "l"(src), "r"(sz) : "memory")
#define CP_COMMIT  asm volatile("cp.async.commit_group;" ::: "memory")
#define CP_WAIT0   asm volatile("cp.async.wait_group 0;" ::: "memory")
#define CP_WAIT1   asm volatile("cp.async.wait_group 1;" ::: "memory")

// ---------------- x -> bf16 hi/lo planes ----------------
__global__ void xsplit_kernel(const float* __restrict__ x, int total4) {
    int i = blockIdx.x * blockDim.x + threadIdx.x;     // over N*32 float4
    if (i >= total4) return;
    float4 v = ((const float4*)x)[i];
    unsigned short h0, h1, h2, h3, l0, l1, l2, l3;
    bf16_split(v.x, h0, l0); bf16_split(v.y, h1, l1);
    bf16_split(v.z, h2, l2); bf16_split(v.w, h3, l3);
    *(uint2*)(g_Xhi + (size_t)i * 4) = make_uint2((uint32_t)h0 | ((uint32_t)h1 << 16),
                                                  (uint32_t)h2 | ((uint32_t)h3 << 16));
    *(uint2*)(g_Xlo + (size_t)i * 4) = make_uint2((uint32_t)l0 | ((uint32_t)l1 << 16),
                                                  (uint32_t)l2 | ((uint32_t)l3 << 16));
}

// ---------------- W transpose + split (destination chosen in DEVICE code) ----------------
__global__ void wsplit_kernel(const float* __restrict__ W, int BN, int which) {
    int idx = blockIdx.x * blockDim.x + threadIdx.x;   // over 128*BN
    if (idx >= 128 * BN) return;
    int k = idx / BN, n = idx % BN;
    unsigned short hi, lo;
    bf16_split(W[idx], hi, lo);
    unsigned short* Whi = which ? g_W2hi : g_W1hi;
    unsigned short* Wlo = which ? g_W2lo : g_W1lo;
    Whi[n * 128 + k] = hi;
    Wlo[n * 128 + k] = lo;
}

// ================= persistent pipelined GEMM: C[N,BN] = A[N,128] @ W[128,BN] ==========
// BM=64 (fine tiles: 782/296 CTAs = max 3, imbalance 1.14x vs 1.51x at BM=128).
// 256 thr = 8 warps (2M x 4N). W planes staged ONCE (LDW=136 shorts, conflict-free).
// A streamed as 4 K-chunks of 32 via depth-2 cp.async pipeline (LDA=40 shorts).
// bf16 m16n8k16, 3-term split: Ahi*Bhi + Ahi*Blo + Alo*Bhi.
template<int BN>
__device__ __forceinline__ void gemm_body(const unsigned short* __restrict__ Ahi,
                                          const unsigned short* __restrict__ Alo,
                                          const unsigned short* __restrict__ Whi,
                                          const unsigned short* __restrict__ Wlo,
                                          float* __restrict__ C, int N, int tiles) {
    constexpr int NT     = BN / 32;       // n8 tiles per warp (BN=128 -> 4, 64 -> 2)
    constexpr int LDW    = 136;           // shorts per W row (128 + 8 pad)
    constexpr int LDA    = 40;            // shorts per A row per chunk (32 + 8 pad)
    constexpr int APLANE = 64 * LDA;
    extern __shared__ unsigned short sus[];
    unsigned short* sW = sus;                     // [2 planes][BN][LDW]
    unsigned short* sA = sus + 2 * BN * LDW;      // [2 buf][2 planes][64][LDA]
    uint32_t sA_addr = smem_u32(sA);
    uint32_t sW_addr = smem_u32(sW);

    int tid  = threadIdx.x;
    int lane = tid & 31, wid = tid >> 5;
    int warpM = wid & 1, warpN = wid >> 1;        // 2 x 4 warp grid
    int grp = lane >> 2, tig = lane & 3;

    // ---- stage W once (both planes, full K) ----
#pragma unroll
    for (int it = 0; it < BN / 8; it++) {
        int idx = tid + it * 256;                  // 2*BN*16 chunks of 16B
        int plane = idx / (BN * 16);
        int rem   = idx - plane * (BN * 16);
        int n = rem >> 4, c = rem & 15;
        const unsigned short* src = (plane ? Wlo : Whi) + n * 128 + c * 8;
        uint32_t dst = sW_addr + (uint32_t)(((plane * BN + n) * LDW + c * 8) * 2);
        CP_ASYNC16(dst, src, 16);
    }

    for (int tile = blockIdx.x; tile < tiles; tile += gridDim.x) {
        int rowBase = tile * 64;
        // issue A chunk 0 into buf 0 (first tile's group also carries W)
        {
#pragma unroll
            for (int it = 0; it < 2; it++) {
                int idx = tid + it * 256;          // 512 chunks of 16B
                int plane = idx >> 8, rem = idx & 255;
                int r = rem >> 2, c = rem & 3;
                int gr = rowBase + r;
                const unsigned short* src = (plane ? Alo : Ahi) + (size_t)gr * 128 + c * 8;
                uint32_t dst = sA_addr + (uint32_t)((((0 * 2 + plane) * 64 + r) * LDA + c * 8) * 2);
                CP_ASYNC16(dst, src, gr < N ? 16 : 0);
            }
            CP_COMMIT;
        }

        float acc[2][NT][4];
#pragma unroll
        for (int mt = 0; mt < 2; mt++)
#pragma unroll
            for (int nt = 0; nt < NT; nt++)
#pragma unroll
                for (int i = 0; i < 4; i++) acc[mt][nt][i] = 0.f;

        int buf = 0;
#pragma unroll
        for (int ch = 0; ch < 4; ch++) {
            if (ch < 3) {
#pragma unroll
                for (int it = 0; it < 2; it++) {
                    int idx = tid + it * 256;
                    int plane = idx >> 8, rem = idx & 255;
                    int r = rem >> 2, c = rem & 3;
                    int gr = rowBase + r;
                    const unsigned short* src =
                        (plane ? Alo : Ahi) + (size_t)gr * 128 + (ch + 1) * 32 + c * 8;
                    uint32_t dst = sA_addr +
                        (uint32_t)(((((buf ^ 1) * 2 + plane) * 64 + r) * LDA + c * 8) * 2);
                    CP_ASYNC16(dst, src, gr < N ? 16 : 0);
                }
                CP_COMMIT;
                CP_WAIT1;
            } else {
                CP_WAIT0;
            }
            __syncthreads();

            const unsigned short* Ah = sA + (buf * 2 + 0) * APLANE;
            const unsigned short* Al = sA + (buf * 2 + 1) * APLANE;
#pragma unroll
            for (int kt = 0; kt < 2; kt++) {
                int ka = kt * 16 + 2 * tig;
                int kw = ch * 32 + ka;
                uint32_t ah[2][4], al[2][4];
#pragma unroll
                for (int mt = 0; mt < 2; mt++) {
                    int r = warpM * 32 + mt * 16 + grp;
                    ah[mt][0] = *(const uint32_t*)(Ah + r       * LDA + ka);
                    ah[mt][1] = *(const uint32_t*)(Ah + (r + 8) * LDA + ka);
                    ah[mt][2] = *(const uint32_t*)(Ah + r       * LDA + ka + 8);
                    ah[mt][3] = *(const uint32_t*)(Ah + (r + 8) * LDA + ka + 8);
                    al[mt][0] = *(const uint32_t*)(Al + r       * LDA + ka);
                    al[mt][1] = *(const uint32_t*)(Al + (r + 8) * LDA + ka);
                    al[mt][2] = *(const uint32_t*)(Al + r       * LDA + ka + 8);
                    al[mt][3] = *(const uint32_t*)(Al + (r + 8) * LDA + ka + 8);
                }
                uint32_t bh[NT][2], bl[NT][2];
#pragma unroll
                for (int nt = 0; nt < NT; nt++) {
                    int n = warpN * (BN / 4) + nt * 8 + grp;
                    bh[nt][0] = *(const uint32_t*)(sW + n * LDW + kw);
                    bh[nt][1] = *(const uint32_t*)(sW + n * LDW + kw + 8);
                    bl[nt][0] = *(const uint32_t*)(sW + (BN + n) * LDW + kw);
                    bl[nt][1] = *(const uint32_t*)(sW + (BN + n) * LDW + kw + 8);
                }
#pragma unroll
                for (int mt = 0; mt < 2; mt++)
#pragma unroll
                    for (int nt = 0; nt < NT; nt++) {
                        mma_bf16(acc[mt][nt], ah[mt], bh[nt]);
                        mma_bf16(acc[mt][nt], ah[mt], bl[nt]);
                        mma_bf16(acc[mt][nt], al[mt], bh[nt]);
                    }
            }
            __syncthreads();
            buf ^= 1;
        }

        // ---- store C ----
#pragma unroll
        for (int mt = 0; mt < 2; mt++) {
            int r0 = rowBase + warpM * 32 + mt * 16 + grp;
#pragma unroll
            for (int nt = 0; nt < NT; nt++) {
                int c = warpN * (BN / 4) + nt * 8 + tig * 2;
                if (r0 < N)
                    *(float2*)(C + (size_t)r0 * BN + c) = make_float2(acc[mt][nt][0], acc[mt][nt][1]);
                if (r0 + 8 < N)
                    *(float2*)(C + (size_t)(r0 + 8) * BN + c) = make_float2(acc[mt][nt][2], acc[mt][nt][3]);
            }
        }
    }
    CP_WAIT0;   // drain (covers CTAs that issued W but got no tile)
}

__global__ __launch_bounds__(256, 2) void gemm1_kernel(int N, int tiles) {
    gemm_body<128>(g_Xhi, g_Xlo, g_W1hi, g_W1lo, g_h1, N, tiles);
}
__global__ __launch_bounds__(256, 2) void gemm2_kernel(int N, int tiles) {
    gemm_body<64>(g_Hhi, g_Hlo, g_W2hi, g_W2lo, g_h2, N, tiles);
}

// ================= CSR build =================
__global__ void zero_count_kernel(int N) {
    int i = blockIdx.x * blockDim.x + threadIdx.x;
    if (i < N) g_count[i] = 0;
}
__global__ void degree_kernel(const int* __restrict__ ei, int E, int N) {
    int e = blockIdx.x * blockDim.x + threadIdx.x;
    if (e >= E) return;
    int d = ei[E + e];
    int p = 0;
    if ((unsigned)d < (unsigned)N) p = atomicAdd(&g_count[d], 1);
    g_rank[e] = p;
}
__global__ void scan_partial_kernel(int N) {
    __shared__ int sh[256];
    int t = threadIdx.x, b = blockIdx.x;
    int i = b * 256 + t;
    sh[t] = (i < N) ? g_count[i] : 0;
    __syncthreads();
    for (int off = 128; off > 0; off >>= 1) {
        if (t < off) sh[t] += sh[t + off];
        __syncthreads();
    }
    if (t == 0) g_bsum[b] = sh[0];
}
__global__ void scan_blocks_kernel(int nb) {
    __shared__ int sh[256];
    int t = threadIdx.x;
    int v = (t < nb) ? g_bsum[t] : 0;
    sh[t] = v;
    __syncthreads();
    for (int off = 1; off < 256; off <<= 1) {
        int a = 0;
        if (t >= off) a = sh[t - off];
        __syncthreads();
        if (t >= off) sh[t] += a;
        __syncthreads();
    }
    if (t < nb) g_boff[t] = sh[t] - v;     // exclusive prefix
}
__global__ void scan_final_kernel(int N) {
    __shared__ int sh[256];
    int t = threadIdx.x, b = blockIdx.x;
    int i = b * 256 + t;
    int c = (i < N) ? g_count[i] : 0;
    sh[t] = c;
    __syncthreads();
    for (int off = 1; off < 256; off <<= 1) {
        int a = 0;
        if (t >= off) a = sh[t - off];
        __syncthreads();
        if (t >= off) sh[t] += a;
        __syncthreads();
    }
    if (i < N) {
        int incl = sh[t] + g_boff[b];
        g_rowptr[i] = incl - c;
        g_dinv[i] = rsqrtf((float)c + 1.0f);
        if (i == N - 1) g_rowptr[N] = incl;
    }
}
__global__ void fill_csr_kernel(const int* __restrict__ ei, int E, int N) {
    int e = blockIdx.x * blockDim.x + threadIdx.x;
    if (e >= E) return;
    int s = ei[e];
    int d = ei[E + e];
    if ((unsigned)d >= (unsigned)N || (unsigned)s >= (unsigned)N) return;
    g_csr[g_rowptr[d] + g_rank[e]] = s;
}

// ================= gathers =================
__global__ void gather128_kernel(const float* __restrict__ b1, int N) {
    int w    = (blockIdx.x * blockDim.x + threadIdx.x) >> 5;
    int lane = threadIdx.x & 31;
    if (w >= N) return;
    int beg = g_rowptr[w], end = g_rowptr[w + 1];
    float4 acc = make_float4(0.f, 0.f, 0.f, 0.f);
    int e = beg;
    for (; e + 1 < end; e += 2) {
        int s0 = g_csr[e], s1 = g_csr[e + 1];
        float w0 = g_dinv[s0], w1 = g_dinv[s1];
        float4 v0 = *(const float4*)(g_h1 + (size_t)s0 * 128 + lane * 4);
        float4 v1 = *(const float4*)(g_h1 + (size_t)s1 * 128 + lane * 4);
        acc.x += w0 * v0.x + w1 * v1.x;
        acc.y += w0 * v0.y + w1 * v1.y;
        acc.z += w0 * v0.z + w1 * v1.z;
        acc.w += w0 * v0.w + w1 * v1.w;
    }
    if (e < end) {
        int s0 = g_csr[e];
        float w0 = g_dinv[s0];
        float4 v0 = *(const float4*)(g_h1 + (size_t)s0 * 128 + lane * 4);
        acc.x += w0 * v0.x; acc.y += w0 * v0.y; acc.z += w0 * v0.z; acc.w += w0 * v0.w;
    }
    float dd = g_dinv[w];
    float d2 = dd * dd;
    float4 self = *(const float4*)(g_h1 + (size_t)w * 128 + lane * 4);
    float4 bv   = *(const float4*)(b1 + lane * 4);
    float4 r;
    r.x = fmaxf(dd * acc.x + d2 * self.x + bv.x, 0.f);
    r.y = fmaxf(dd * acc.y + d2 * self.y + bv.y, 0.f);
    r.z = fmaxf(dd * acc.z + d2 * self.z + bv.z, 0.f);
    r.w = fmaxf(dd * acc.w + d2 * self.w + bv.w, 0.f);
    unsigned short h0, h1v, h2v, h3, l0, l1v, l2v, l3;
    bf16_split(r.x, h0, l0); bf16_split(r.y, h1v, l1v);
    bf16_split(r.z, h2v, l2v); bf16_split(r.w, h3, l3);
    size_t off = (size_t)w * 128 + lane * 4;
    *(uint2*)(g_Hhi + off) = make_uint2((uint32_t)h0 | ((uint32_t)h1v << 16),
                                        (uint32_t)h2v | ((uint32_t)h3 << 16));
    *(uint2*)(g_Hlo + off) = make_uint2((uint32_t)l0 | ((uint32_t)l1v << 16),
                                        (uint32_t)l2v | ((uint32_t)l3 << 16));
}
__global__ void gather64_kernel(const float* __restrict__ b2, float* __restrict__ out, int N) {
    int w    = (blockIdx.x * blockDim.x + threadIdx.x) >> 5;
    int lane = threadIdx.x & 31;
    if (w >= N) return;
    int beg = g_rowptr[w], end = g_rowptr[w + 1];
    float2 acc = make_float2(0.f, 0.f);
    int e = beg;
    for (; e + 1 < end; e += 2) {
        int s0 = g_csr[e], s1 = g_csr[e + 1];
        float w0 = g_dinv[s0], w1 = g_dinv[s1];
        float2 v0 = *(const float2*)(g_h2 + (size_t)s0 * 64 + lane * 2);
        float2 v1 = *(const float2*)(g_h2 + (size_t)s1 * 64 + lane * 2);
        acc.x += w0 * v0.x + w1 * v1.x;
        acc.y += w0 * v0.y + w1 * v1.y;
    }
    if (e < end) {
        int s0 = g_csr[e];
        float w0 = g_dinv[s0];
        float2 v0 = *(const float2*)(g_h2 + (size_t)s0 * 64 + lane * 2);
        acc.x += w0 * v0.x; acc.y += w0 * v0.y;
    }
    float dd = g_dinv[w];
    float d2 = dd * dd;
    float2 self = *(const float2*)(g_h2 + (size_t)w * 64 + lane * 2);
    float2 bv   = *(const float2*)(b2 + lane * 2);
    float2 r;
    r.x = dd * acc.x + d2 * self.x + bv.x;
    r.y = dd * acc.y + d2 * self.y + bv.y;
    *(float2*)(out + (size_t)w * 64 + lane * 2) = r;
}

// ================= launch =================
extern "C" void kernel_launch(void* const* d_in, const int* in_sizes, int n_in,
                              void* d_out, int out_size) {
    const float* x  = (const float*)d_in[0];
    const int*   ei = (const int*)d_in[1];     // int32 (JAX x64 disabled)
    const float* W1 = (const float*)d_in[2];
    const float* b1 = (const float*)d_in[3];
    const float* W2 = (const float*)d_in[4];
    const float* b2 = (const float*)d_in[5];
    float* out = (float*)d_out;

    int N = in_sizes[0] / 128;
    int E = in_sizes[1] / 2;
    if (N > N_MAX) N = N_MAX;
    if (E > E_MAX) E = E_MAX;

    const int TPB = 256;
    int tiles = (N + 63) / 64;
    int nb    = (N + 255) / 256;

    constexpr int SMEM1 = (2 * 128 * 136 + 2 * 2 * 64 * 40) * 2;   // 90112 B -> 2 CTAs/SM
    constexpr int SMEM2 = (2 * 64  * 136 + 2 * 2 * 64 * 40) * 2;   // 55296 B -> 2 CTAs/SM
    cudaFuncSetAttribute(gemm1_kernel, cudaFuncAttributeMaxDynamicSharedMemorySize, SMEM1);
    cudaFuncSetAttribute(gemm2_kernel, cudaFuncAttributeMaxDynamicSharedMemorySize, SMEM2);

    // Dual-stream fork/join (graph-capturable): CSR chain runs concurrent with the
    // x/W split + gemm1 chain. Created per call; destroyed only when not capturing
    // (capture happens once; replays execute only the captured GPU nodes).
    cudaStream_t sB = 0;
    cudaStreamCreateWithFlags(&sB, cudaStreamNonBlocking);
    cudaEvent_t evF, evJ;
    cudaEventCreateWithFlags(&evF, cudaEventDisableTiming);
    cudaEventCreateWithFlags(&evJ, cudaEventDisableTiming);

    cudaEventRecord(evF, 0);
    cudaStreamWaitEvent(sB, evF, 0);

    // launch order keeps gemm1 as my 4th kernel launch (the ncu-profiled slot)
    zero_count_kernel<<<(N + TPB - 1) / TPB, TPB, 0, sB>>>(N);               // 0 (sB)
    xsplit_kernel<<<(N * 32 + TPB - 1) / TPB, TPB>>>(x, N * 32);             // 1 (s0)
    wsplit_kernel<<<(128 * 128 + TPB - 1) / TPB, TPB>>>(W1, 128, 0);         // 2 (s0)
    gemm1_kernel<<<296, 256, SMEM1>>>(N, tiles);                             // 3 (s0) <- profiled

    degree_kernel<<<(E + TPB - 1) / TPB, TPB, 0, sB>>>(ei, E, N);            // (sB)
    scan_partial_kernel<<<nb, 256, 0, sB>>>(N);                              // (sB)
    scan_blocks_kernel<<<1, 256, 0, sB>>>(nb);                               // (sB)
    scan_final_kernel<<<nb, 256, 0, sB>>>(N);                                // (sB)
    fill_csr_kernel<<<(E + TPB - 1) / TPB, TPB, 0, sB>>>(ei, E, N);          // (sB)
    wsplit_kernel<<<(128 * 64 + TPB - 1) / TPB, TPB, 0, sB>>>(W2, 64, 1);    // (sB)

    cudaEventRecord(evJ, sB);
    cudaStreamWaitEvent(0, evJ, 0);

    {
        long long tot = (long long)N * 32;
        gather128_kernel<<<(int)((tot + TPB - 1) / TPB), TPB>>>(b1, N);      // (s0)
    }
    gemm2_kernel<<<296, 256, SMEM2>>>(N, tiles);                             // (s0)
    {
        long long tot = (long long)N * 32;
        gather64_kernel<<<(int)((tot + TPB - 1) / TPB), TPB>>>(b2, out, N);  // (s0)
    }

    cudaStreamCaptureStatus cap = cudaStreamCaptureStatusNone;
    cudaStreamIsCapturing(sB, &cap);
    if (cap == cudaStreamCaptureStatusNone) {
        cudaEventDestroy(evF);
        cudaEventDestroy(evJ);
        cudaStreamDestroy(sB);
    }
}

// round 16
// speedup vs baseline: 1.9969x; 1.0353x over previous
#include <cuda_runtime.h>
#include <cuda_bf16.h>
#include <cuda_fp16.h>
#include <cstdint>

#define N_MAX 50000
#define E_MAX 800000

// ---------------- scratch (device globals; referenced ONLY in device code) ----------
__device__ int    g_count [N_MAX];
__device__ int    g_rowptr[N_MAX + 1];
__device__ int    g_rank  [E_MAX];
__device__ int    g_csr   [E_MAX];
__device__ int    g_bsum  [256];
__device__ int    g_boff  [256];
__device__ float  g_dinv  [N_MAX];
__device__ __half g_h1    [(size_t)N_MAX * 128];   // x@W1, fp16 (gather reads half bytes)
__device__ __half g_h2    [(size_t)N_MAX * 64];    // hrelu@W2, fp16
// bf16 hi/lo planes, [row][k] (k contiguous)
__device__ unsigned short g_Xhi[(size_t)N_MAX * 128];
__device__ unsigned short g_Xlo[(size_t)N_MAX * 128];
__device__ unsigned short g_Hhi[(size_t)N_MAX * 128];
__device__ unsigned short g_Hlo[(size_t)N_MAX * 128];
__device__ unsigned short g_W1hi[128 * 128];
__device__ unsigned short g_W1lo[128 * 128];
__device__ unsigned short g_W2hi[64 * 128];
__device__ unsigned short g_W2lo[64 * 128];

// ---------------- helpers ----------------
__device__ __forceinline__ uint32_t smem_u32(const void* p) {
    uint32_t a;
    asm("{ .reg .u64 t; cvta.to.shared.u64 t, %1; cvt.u32.u64 %0, t; }" : "=r"(a) : "l"(p));
    return a;
}
__device__ __forceinline__ void bf16_split(float x, unsigned short& hi, unsigned short& lo) {
    __nv_bfloat16 h = __float2bfloat16(x);
    float r = x - __bfloat162float(h);
    __nv_bfloat16 l = __float2bfloat16(r);
    hi = *reinterpret_cast<unsigned short*>(&h);
    lo = *reinterpret_cast<unsigned short*>(&l);
}
__device__ __forceinline__ void mma_bf16(float* c, const uint32_t* a, const uint32_t* b) {
    asm volatile(
        "mma.sync.aligned.m16n8k16.row.col.f32.bf16.bf16.f32 "
        "{%0,%1,%2,%3}, {%4,%5,%6,%7}, {%8,%9}, {%0,%1,%2,%3};"
        : "+f"(c[0]), "+f"(c[1]), "+f"(c[2]), "+f"(c[3])
        : "r"(a[0]), "r"(a[1]), "r"(a[2]), "r"(a[3]), "r"(b[0]), "r"(b[1]));
}
__device__ __forceinline__ float4 ld_half4(const __half* p) {
    uint2 u = *(const uint2*)p;
    __half2 a = *reinterpret_cast<__half2*>(&u.x);
    __half2 b = *reinterpret_cast<__half2*>(&u.y);
    float2 fa = __half22float2(a), fb = __half22float2(b);
    return make_float4(fa.x, fa.y, fb.x, fb.y);
}
#define CP_ASYNC16(dst, src, sz) \
    asm volatile("cp.async.cg.shared.global [%0], [%1], 16, %2;" \
                 :: "r"(dst), "l"(src), "r"(sz) : "memory")
#define CP_COMMIT  asm volatile("cp.async.commit_group;" ::: "memory")
#define CP_WAIT0   asm volatile("cp.async.wait_group 0;" ::: "memory")
#define CP_WAIT1   asm volatile("cp.async.wait_group 1;" ::: "memory")

// ---------------- x -> bf16 hi/lo planes ----------------
__global__ void xsplit_kernel(const float* __restrict__ x, int total4) {
    int i = blockIdx.x * blockDim.x + threadIdx.x;     // over N*32 float4
    if (i >= total4) return;
    float4 v = ((const float4*)x)[i];
    unsigned short h0, h1, h2, h3, l0, l1, l2, l3;
    bf16_split(v.x, h0, l0); bf16_split(v.y, h1, l1);
    bf16_split(v.z, h2, l2); bf16_split(v.w, h3, l3);
    *(uint2*)(g_Xhi + (size_t)i * 4) = make_uint2((uint32_t)h0 | ((uint32_t)h1 << 16),
                                                  (uint32_t)h2 | ((uint32_t)h3 << 16));
    *(uint2*)(g_Xlo + (size_t)i * 4) = make_uint2((uint32_t)l0 | ((uint32_t)l1 << 16),
                                                  (uint32_t)l2 | ((uint32_t)l3 << 16));
}

// ---------------- W transpose + split (destination chosen in DEVICE code) ----------------
__global__ void wsplit_kernel(const float* __restrict__ W, int BN, int which) {
    int idx = blockIdx.x * blockDim.x + threadIdx.x;   // over 128*BN
    if (idx >= 128 * BN) return;
    int k = idx / BN, n = idx % BN;
    unsigned short hi, lo;
    bf16_split(W[idx], hi, lo);
    unsigned short* Whi = which ? g_W2hi : g_W1hi;
    unsigned short* Wlo = which ? g_W2lo : g_W1lo;
    Whi[n * 128 + k] = hi;
    Wlo[n * 128 + k] = lo;
}

// ================= persistent pipelined GEMM: C[N,BN] = A[N,128] @ W[128,BN] ==========
// BM=64 fine tiles; 256 thr = 8 warps (2M x 4N). W staged once (LDW=136 shorts).
// A via depth-2 cp.async pipeline (LDA=40 shorts). bf16 m16n8k16, 3-term split.
// C stored as fp16 (__half2) — halves downstream gather bytes.
template<int BN>
__device__ __forceinline__ void gemm_body(const unsigned short* __restrict__ Ahi,
                                          const unsigned short* __restrict__ Alo,
                                          const unsigned short* __restrict__ Whi,
                                          const unsigned short* __restrict__ Wlo,
                                          __half* __restrict__ C, int N, int tiles) {
    constexpr int NT     = BN / 32;
    constexpr int LDW    = 136;
    constexpr int LDA    = 40;
    constexpr int APLANE = 64 * LDA;
    extern __shared__ unsigned short sus[];
    unsigned short* sW = sus;                     // [2 planes][BN][LDW]
    unsigned short* sA = sus + 2 * BN * LDW;      // [2 buf][2 planes][64][LDA]
    uint32_t sA_addr = smem_u32(sA);
    uint32_t sW_addr = smem_u32(sW);

    int tid  = threadIdx.x;
    int lane = tid & 31, wid = tid >> 5;
    int warpM = wid & 1, warpN = wid >> 1;        // 2 x 4 warp grid
    int grp = lane >> 2, tig = lane & 3;

    // ---- stage W once (both planes, full K) ----
#pragma unroll
    for (int it = 0; it < BN / 8; it++) {
        int idx = tid + it * 256;
        int plane = idx / (BN * 16);
        int rem   = idx - plane * (BN * 16);
        int n = rem >> 4, c = rem & 15;
        const unsigned short* src = (plane ? Wlo : Whi) + n * 128 + c * 8;
        uint32_t dst = sW_addr + (uint32_t)(((plane * BN + n) * LDW + c * 8) * 2);
        CP_ASYNC16(dst, src, 16);
    }

    for (int tile = blockIdx.x; tile < tiles; tile += gridDim.x) {
        int rowBase = tile * 64;
        {
#pragma unroll
            for (int it = 0; it < 2; it++) {
                int idx = tid + it * 256;
                int plane = idx >> 8, rem = idx & 255;
                int r = rem >> 2, c = rem & 3;
                int gr = rowBase + r;
                const unsigned short* src = (plane ? Alo : Ahi) + (size_t)gr * 128 + c * 8;
                uint32_t dst = sA_addr + (uint32_t)((((0 * 2 + plane) * 64 + r) * LDA + c * 8) * 2);
                CP_ASYNC16(dst, src, gr < N ? 16 : 0);
            }
            CP_COMMIT;
        }

        float acc[2][NT][4];
#pragma unroll
        for (int mt = 0; mt < 2; mt++)
#pragma unroll
            for (int nt = 0; nt < NT; nt++)
#pragma unroll
                for (int i = 0; i < 4; i++) acc[mt][nt][i] = 0.f;

        int buf = 0;
#pragma unroll
        for (int ch = 0; ch < 4; ch++) {
            if (ch < 3) {
#pragma unroll
                for (int it = 0; it < 2; it++) {
                    int idx = tid + it * 256;
                    int plane = idx >> 8, rem = idx & 255;
                    int r = rem >> 2, c = rem & 3;
                    int gr = rowBase + r;
                    const unsigned short* src =
                        (plane ? Alo : Ahi) + (size_t)gr * 128 + (ch + 1) * 32 + c * 8;
                    uint32_t dst = sA_addr +
                        (uint32_t)(((((buf ^ 1) * 2 + plane) * 64 + r) * LDA + c * 8) * 2);
                    CP_ASYNC16(dst, src, gr < N ? 16 : 0);
                }
                CP_COMMIT;
                CP_WAIT1;
            } else {
                CP_WAIT0;
            }
            __syncthreads();

            const unsigned short* Ah = sA + (buf * 2 + 0) * APLANE;
            const unsigned short* Al = sA + (buf * 2 + 1) * APLANE;
#pragma unroll
            for (int kt = 0; kt < 2; kt++) {
                int ka = kt * 16 + 2 * tig;
                int kw = ch * 32 + ka;
                uint32_t ah[2][4], al[2][4];
#pragma unroll
                for (int mt = 0; mt < 2; mt++) {
                    int r = warpM * 32 + mt * 16 + grp;
                    ah[mt][0] = *(const uint32_t*)(Ah + r       * LDA + ka);
                    ah[mt][1] = *(const uint32_t*)(Ah + (r + 8) * LDA + ka);
                    ah[mt][2] = *(const uint32_t*)(Ah + r       * LDA + ka + 8);
                    ah[mt][3] = *(const uint32_t*)(Ah + (r + 8) * LDA + ka + 8);
                    al[mt][0] = *(const uint32_t*)(Al + r       * LDA + ka);
                    al[mt][1] = *(const uint32_t*)(Al + (r + 8) * LDA + ka);
                    al[mt][2] = *(const uint32_t*)(Al + r       * LDA + ka + 8);
                    al[mt][3] = *(const uint32_t*)(Al + (r + 8) * LDA + ka + 8);
                }
                uint32_t bh[NT][2], bl[NT][2];
#pragma unroll
                for (int nt = 0; nt < NT; nt++) {
                    int n = warpN * (BN / 4) + nt * 8 + grp;
                    bh[nt][0] = *(const uint32_t*)(sW + n * LDW + kw);
                    bh[nt][1] = *(const uint32_t*)(sW + n * LDW + kw + 8);
                    bl[nt][0] = *(const uint32_t*)(sW + (BN + n) * LDW + kw);
                    bl[nt][1] = *(const uint32_t*)(sW + (BN + n) * LDW + kw + 8);
                }
#pragma unroll
                for (int mt = 0; mt < 2; mt++)
#pragma unroll
                    for (int nt = 0; nt < NT; nt++) {
                        mma_bf16(acc[mt][nt], ah[mt], bh[nt]);
                        mma_bf16(acc[mt][nt], ah[mt], bl[nt]);
                        mma_bf16(acc[mt][nt], al[mt], bh[nt]);
                    }
            }
            __syncthreads();
            buf ^= 1;
        }

        // ---- store C as fp16 ----
#pragma unroll
        for (int mt = 0; mt < 2; mt++) {
            int r0 = rowBase + warpM * 32 + mt * 16 + grp;
#pragma unroll
            for (int nt = 0; nt < NT; nt++) {
                int c = warpN * (BN / 4) + nt * 8 + tig * 2;
                if (r0 < N)
                    *(__half2*)(C + (size_t)r0 * BN + c) =
                        __floats2half2_rn(acc[mt][nt][0], acc[mt][nt][1]);
                if (r0 + 8 < N)
                    *(__half2*)(C + (size_t)(r0 + 8) * BN + c) =
                        __floats2half2_rn(acc[mt][nt][2], acc[mt][nt][3]);
            }
        }
    }
    CP_WAIT0;
}

__global__ __launch_bounds__(256, 2) void gemm1_kernel(int N, int tiles) {
    gemm_body<128>(g_Xhi, g_Xlo, g_W1hi, g_W1lo, g_h1, N, tiles);
}
__global__ __launch_bounds__(256, 2) void gemm2_kernel(int N, int tiles) {
    gemm_body<64>(g_Hhi, g_Hlo, g_W2hi, g_W2lo, g_h2, N, tiles);
}

// ================= CSR build =================
__global__ void zero_count_kernel(int N) {
    int i = blockIdx.x * blockDim.x + threadIdx.x;
    if (i < N) g_count[i] = 0;
}
__global__ void degree_kernel(const int* __restrict__ ei, int E, int N) {
    int e = blockIdx.x * blockDim.x + threadIdx.x;
    if (e >= E) return;
    int d = ei[E + e];
    int p = 0;
    if ((unsigned)d < (unsigned)N) p = atomicAdd(&g_count[d], 1);
    g_rank[e] = p;
}
__global__ void scan_partial_kernel(int N) {
    __shared__ int sh[256];
    int t = threadIdx.x, b = blockIdx.x;
    int i = b * 256 + t;
    sh[t] = (i < N) ? g_count[i] : 0;
    __syncthreads();
    for (int off = 128; off > 0; off >>= 1) {
        if (t < off) sh[t] += sh[t + off];
        __syncthreads();
    }
    if (t == 0) g_bsum[b] = sh[0];
}
__global__ void scan_blocks_kernel(int nb) {
    __shared__ int sh[256];
    int t = threadIdx.x;
    int v = (t < nb) ? g_bsum[t] : 0;
    sh[t] = v;
    __syncthreads();
    for (int off = 1; off < 256; off <<= 1) {
        int a = 0;
        if (t >= off) a = sh[t - off];
        __syncthreads();
        if (t >= off) sh[t] += a;
        __syncthreads();
    }
    if (t < nb) g_boff[t] = sh[t] - v;
}
__global__ void scan_final_kernel(int N) {
    __shared__ int sh[256];
    int t = threadIdx.x, b = blockIdx.x;
    int i = b * 256 + t;
    int c = (i < N) ? g_count[i] : 0;
    sh[t] = c;
    __syncthreads();
    for (int off = 1; off < 256; off <<= 1) {
        int a = 0;
        if (t >= off) a = sh[t - off];
        __syncthreads();
        if (t >= off) sh[t] += a;
        __syncthreads();
    }
    if (i < N) {
        int incl = sh[t] + g_boff[b];
        g_rowptr[i] = incl - c;
        g_dinv[i] = rsqrtf((float)c + 1.0f);
        if (i == N - 1) g_rowptr[N] = incl;
    }
}
__global__ void fill_csr_kernel(const int* __restrict__ ei, int E, int N) {
    int e = blockIdx.x * blockDim.x + threadIdx.x;
    if (e >= E) return;
    int s = ei[e];
    int d = ei[E + e];
    if ((unsigned)d >= (unsigned)N || (unsigned)s >= (unsigned)N) return;
    g_csr[g_rowptr[d] + g_rank[e]] = s;
}

// ================= gathers (fp16 reads, fp32 accumulate) =================
__global__ void gather128_kernel(const float* __restrict__ b1, int N) {
    int w    = (blockIdx.x * blockDim.x + threadIdx.x) >> 5;
    int lane = threadIdx.x & 31;
    if (w >= N) return;
    int beg = g_rowptr[w], end = g_rowptr[w + 1];
    float4 acc = make_float4(0.f, 0.f, 0.f, 0.f);
    int e = beg;
    for (; e + 1 < end; e += 2) {
        int s0 = g_csr[e], s1 = g_csr[e + 1];
        float w0 = g_dinv[s0], w1 = g_dinv[s1];
        float4 v0 = ld_half4(g_h1 + (size_t)s0 * 128 + lane * 4);
        float4 v1 = ld_half4(g_h1 + (size_t)s1 * 128 + lane * 4);
        acc.x += w0 * v0.x + w1 * v1.x;
        acc.y += w0 * v0.y + w1 * v1.y;
        acc.z += w0 * v0.z + w1 * v1.z;
        acc.w += w0 * v0.w + w1 * v1.w;
    }
    if (e < end) {
        int s0 = g_csr[e];
        float w0 = g_dinv[s0];
        float4 v0 = ld_half4(g_h1 + (size_t)s0 * 128 + lane * 4);
        acc.x += w0 * v0.x; acc.y += w0 * v0.y; acc.z += w0 * v0.z; acc.w += w0 * v0.w;
    }
    float dd = g_dinv[w];
    float d2 = dd * dd;
    float4 self = ld_half4(g_h1 + (size_t)w * 128 + lane * 4);
    float4 bv   = *(const float4*)(b1 + lane * 4);
    float4 r;
    r.x = fmaxf(dd * acc.x + d2 * self.x + bv.x, 0.f);
    r.y = fmaxf(dd * acc.y + d2 * self.y + bv.y, 0.f);
    r.z = fmaxf(dd * acc.z + d2 * self.z + bv.z, 0.f);
    r.w = fmaxf(dd * acc.w + d2 * self.w + bv.w, 0.f);
    unsigned short h0, h1v, h2v, h3, l0, l1v, l2v, l3;
    bf16_split(r.x, h0, l0); bf16_split(r.y, h1v, l1v);
    bf16_split(r.z, h2v, l2v); bf16_split(r.w, h3, l3);
    size_t off = (size_t)w * 128 + lane * 4;
    *(uint2*)(g_Hhi + off) = make_uint2((uint32_t)h0 | ((uint32_t)h1v << 16),
                                        (uint32_t)h2v | ((uint32_t)h3 << 16));
    *(uint2*)(g_Hlo + off) = make_uint2((uint32_t)l0 | ((uint32_t)l1v << 16),
                                        (uint32_t)l2v | ((uint32_t)l3 << 16));
}
__global__ void gather64_kernel(const float* __restrict__ b2, float* __restrict__ out, int N) {
    int w    = (blockIdx.x * blockDim.x + threadIdx.x) >> 5;
    int lane = threadIdx.x & 31;
    if (w >= N) return;
    int beg = g_rowptr[w], end = g_rowptr[w + 1];
    float2 acc = make_float2(0.f, 0.f);
    int e = beg;
    for (; e + 1 < end; e += 2) {
        int s0 = g_csr[e], s1 = g_csr[e + 1];
        float w0 = g_dinv[s0], w1 = g_dinv[s1];
        float2 v0 = __half22float2(*(const __half2*)(g_h2 + (size_t)s0 * 64 + lane * 2));
        float2 v1 = __half22float2(*(const __half2*)(g_h2 + (size_t)s1 * 64 + lane * 2));
        acc.x += w0 * v0.x + w1 * v1.x;
        acc.y += w0 * v0.y + w1 * v1.y;
    }
    if (e < end) {
        int s0 = g_csr[e];
        float w0 = g_dinv[s0];
        float2 v0 = __half22float2(*(const __half2*)(g_h2 + (size_t)s0 * 64 + lane * 2));
        acc.x += w0 * v0.x; acc.y += w0 * v0.y;
    }
    float dd = g_dinv[w];
    float d2 = dd * dd;
    float2 self = __half22float2(*(const __half2*)(g_h2 + (size_t)w * 64 + lane * 2));
    float2 bv   = *(const float2*)(b2 + lane * 2);
    float2 r;
    r.x = dd * acc.x + d2 * self.x + bv.x;
    r.y = dd * acc.y + d2 * self.y + bv.y;
    *(float2*)(out + (size_t)w * 64 + lane * 2) = r;
}

// ================= launch =================
extern "C" void kernel_launch(void* const* d_in, const int* in_sizes, int n_in,
                              void* d_out, int out_size) {
    const float* x  = (const float*)d_in[0];
    const int*   ei = (const int*)d_in[1];     // int32 (JAX x64 disabled)
    const float* W1 = (const float*)d_in[2];
    const float* b1 = (const float*)d_in[3];
    const float* W2 = (const float*)d_in[4];
    const float* b2 = (const float*)d_in[5];
    float* out = (float*)d_out;

    int N = in_sizes[0] / 128;
    int E = in_sizes[1] / 2;
    if (N > N_MAX) N = N_MAX;
    if (E > E_MAX) E = E_MAX;

    const int TPB = 256;
    int tiles = (N + 63) / 64;
    int nb    = (N + 255) / 256;

    constexpr int SMEM1 = (2 * 128 * 136 + 2 * 2 * 64 * 40) * 2;   // 90112 B -> 2 CTAs/SM
    constexpr int SMEM2 = (2 * 64  * 136 + 2 * 2 * 64 * 40) * 2;   // 55296 B -> 2 CTAs/SM
    cudaFuncSetAttribute(gemm1_kernel, cudaFuncAttributeMaxDynamicSharedMemorySize, SMEM1);
    cudaFuncSetAttribute(gemm2_kernel, cudaFuncAttributeMaxDynamicSharedMemorySize, SMEM2);

    // Dual-stream fork/join (graph-capturable); resources freed only when not capturing.
    cudaStream_t sB = 0;
    cudaStreamCreateWithFlags(&sB, cudaStreamNonBlocking);
    cudaEvent_t evF, evJ;
    cudaEventCreateWithFlags(&evF, cudaEventDisableTiming);
    cudaEventCreateWithFlags(&evJ, cudaEventDisableTiming);

    cudaEventRecord(evF, 0);
    cudaStreamWaitEvent(sB, evF, 0);

    // launch order keeps gemm1 as my 4th kernel launch (the ncu-profiled slot)
    zero_count_kernel<<<(N + TPB - 1) / TPB, TPB, 0, sB>>>(N);               // 0 (sB)
    xsplit_kernel<<<(N * 32 + TPB - 1) / TPB, TPB>>>(x, N * 32);             // 1 (s0)
    wsplit_kernel<<<(128 * 128 + TPB - 1) / TPB, TPB>>>(W1, 128, 0);         // 2 (s0)
    gemm1_kernel<<<296, 256, SMEM1>>>(N, tiles);                             // 3 (s0) <- profiled

    degree_kernel<<<(E + TPB - 1) / TPB, TPB, 0, sB>>>(ei, E, N);            // (sB)
    scan_partial_kernel<<<nb, 256, 0, sB>>>(N);                              // (sB)
    scan_blocks_kernel<<<1, 256, 0, sB>>>(nb);                               // (sB)
    scan_final_kernel<<<nb, 256, 0, sB>>>(N);                                // (sB)
    fill_csr_kernel<<<(E + TPB - 1) / TPB, TPB, 0, sB>>>(ei, E, N);          // (sB)
    wsplit_kernel<<<(128 * 64 + TPB - 1) / TPB, TPB, 0, sB>>>(W2, 64, 1);    // (sB)

    cudaEventRecord(evJ, sB);
    cudaStreamWaitEvent(0, evJ, 0);

    {
        long long tot = (long long)N * 32;
        gather128_kernel<<<(int)((tot + TPB - 1) / TPB), TPB>>>(b1, N);      // (s0)
    }
    gemm2_kernel<<<296, 256, SMEM2>>>(N, tiles);                             // (s0)
    {
        long long tot = (long long)N * 32;
        gather64_kernel<<<(int)((tot + TPB - 1) / TPB), TPB>>>(b2, out, N);  // (s0)
    }

    cudaStreamCaptureStatus cap = cudaStreamCaptureStatusNone;
    cudaStreamIsCapturing(sB, &cap);
    if (cap == cudaStreamCaptureStatusNone) {
        cudaEventDestroy(evF);
        cudaEventDestroy(evJ);
        cudaStreamDestroy(sB);
    }
}

// round 17
// speedup vs baseline: 2.0616x; 1.0324x over previous
#include <cuda_runtime.h>
#include <cuda_bf16.h>
#include <cuda_fp16.h>
#include <cstdint>

#define N_MAX 50000
#define E_MAX 800000

// ---------------- scratch (device globals; referenced ONLY in device code) ----------
__device__ int    g_count [N_MAX];
__device__ int    g_rowptr[N_MAX + 1];
__device__ int    g_rank  [E_MAX];
__device__ int    g_csr   [E_MAX];
__device__ int    g_bsum  [256];
__device__ int    g_boff  [256];
__device__ float  g_dinv  [N_MAX];
__device__ __half g_h1    [(size_t)N_MAX * 128];   // x@W1, fp16
__device__ __half g_h2    [(size_t)N_MAX * 64];    // hrelu@W2, fp16
// bf16 hi/lo planes for gemm2 input (written by gather128)
__device__ unsigned short g_Hhi[(size_t)N_MAX * 128];
__device__ unsigned short g_Hlo[(size_t)N_MAX * 128];
__device__ unsigned short g_W1hi[128 * 128];
__device__ unsigned short g_W1lo[128 * 128];
__device__ unsigned short g_W2hi[64 * 128];
__device__ unsigned short g_W2lo[64 * 128];

// ---------------- helpers ----------------
__device__ __forceinline__ uint32_t smem_u32(const void* p) {
    uint32_t a;
    asm("{ .reg .u64 t; cvta.to.shared.u64 t, %1; cvt.u32.u64 %0, t; }" : "=r"(a) : "l"(p));
    return a;
}
__device__ __forceinline__ void bf16_split(float x, unsigned short& hi, unsigned short& lo) {
    __nv_bfloat16 h = __float2bfloat16(x);
    float r = x - __bfloat162float(h);
    __nv_bfloat16 l = __float2bfloat16(r);
    hi = *reinterpret_cast<unsigned short*>(&h);
    lo = *reinterpret_cast<unsigned short*>(&l);
}
__device__ __forceinline__ void mma_bf16(float* c, const uint32_t* a, const uint32_t* b) {
    asm volatile(
        "mma.sync.aligned.m16n8k16.row.col.f32.bf16.bf16.f32 "
        "{%0,%1,%2,%3}, {%4,%5,%6,%7}, {%8,%9}, {%0,%1,%2,%3};"
        : "+f"(c[0]), "+f"(c[1]), "+f"(c[2]), "+f"(c[3])
        : "r"(a[0]), "r"(a[1]), "r"(a[2]), "r"(a[3]), "r"(b[0]), "r"(b[1]));
}
__device__ __forceinline__ float4 ld_half4(const __half* p) {
    uint2 u = *(const uint2*)p;
    __half2 a = *reinterpret_cast<__half2*>(&u.x);
    __half2 b = *reinterpret_cast<__half2*>(&u.y);
    float2 fa = __half22float2(a), fb = __half22float2(b);
    return make_float4(fa.x, fa.y, fb.x, fb.y);
}
#define CP_ASYNC16(dst, src, sz) \
    asm volatile("cp.async.cg.shared.global [%0], [%1], 16, %2;" \
                 :: "r"(dst), "l"(src), "r"(sz) : "memory")
#define CP_COMMIT  asm volatile("cp.async.commit_group;" ::: "memory")
#define CP_WAIT0   asm volatile("cp.async.wait_group 0;" ::: "memory")

// ---------------- W transpose + split (destination chosen in DEVICE code) ----------------
__global__ void wsplit_kernel(const float* __restrict__ W, int BN, int which) {
    int idx = blockIdx.x * blockDim.x + threadIdx.x;   // over 128*BN
    if (idx >= 128 * BN) return;
    int k = idx / BN, n = idx % BN;
    unsigned short hi, lo;
    bf16_split(W[idx], hi, lo);
    unsigned short* Whi = which ? g_W2hi : g_W1hi;
    unsigned short* Wlo = which ? g_W2lo : g_W1lo;
    Whi[n * 128 + k] = hi;
    Wlo[n * 128 + k] = lo;
}

// ================= persistent GEMM: C[N,BN] = A[N,128] @ W[128,BN] =================
// BM=64, full K=128 staged per tile in ONE step (2 barriers/tile). W staged once.
// FP32SRC: A is fp32 (split to bf16 hi/lo during STS — xsplit fused away).
// else:    A is pre-split bf16 hi/lo planes.
// Row stride LDK=136 shorts (68 words == 4 mod 32 -> conflict-free fragments).
// bf16 m16n8k16, 3-term split: Ahi*Bhi + Ahi*Blo + Alo*Bhi. C stored fp16.
template<int BN, bool FP32SRC>
__device__ __forceinline__ void gemm_body(const float* __restrict__ Af,
                                          const unsigned short* __restrict__ Ahi,
                                          const unsigned short* __restrict__ Alo,
                                          const unsigned short* __restrict__ Whi,
                                          const unsigned short* __restrict__ Wlo,
                                          __half* __restrict__ C, int N, int tiles) {
    constexpr int NT  = BN / 32;
    constexpr int LDK = 136;
    extern __shared__ unsigned short sus[];
    unsigned short* sW    = sus;                   // [2 planes][BN][LDK]
    unsigned short* sA_hi = sus + 2 * BN * LDK;    // [64][LDK]
    unsigned short* sA_lo = sA_hi + 64 * LDK;
    uint32_t sW_addr = smem_u32(sW);

    int tid  = threadIdx.x;
    int lane = tid & 31, wid = tid >> 5;
    int warpM = wid & 1, warpN = wid >> 1;         // 2 x 4 warp grid
    int grp = lane >> 2, tig = lane & 3;

    // ---- stage W once (both planes, full K) via cp.async ----
#pragma unroll
    for (int it = 0; it < BN / 8; it++) {
        int idx = tid + it * 256;                  // 2*BN*16 chunks of 16B
        int plane = idx / (BN * 16);
        int rem   = idx - plane * (BN * 16);
        int n = rem >> 4, c = rem & 15;
        const unsigned short* src = (plane ? Wlo : Whi) + n * 128 + c * 8;
        uint32_t dst = sW_addr + (uint32_t)(((plane * BN + n) * LDK + c * 8) * 2);
        CP_ASYNC16(dst, src, 16);
    }
    CP_COMMIT;
    CP_WAIT0;
    __syncthreads();

    for (int tile = blockIdx.x; tile < tiles; tile += gridDim.x) {
        int rowBase = tile * 64;

        // ---- stage full A tile (64 x 128) ----
        if (FP32SRC) {
#pragma unroll
            for (int it = 0; it < 8; it++) {
                int idx = tid + it * 256;          // 2048 float4 over 64x32
                int r = idx >> 5, c4 = idx & 31;
                int gr = rowBase + r;
                float4 v = make_float4(0.f, 0.f, 0.f, 0.f);
                if (gr < N) v = *(const float4*)(Af + (size_t)gr * 128 + c4 * 4);
                unsigned short h0, h1, h2, h3, l0, l1, l2, l3;
                bf16_split(v.x, h0, l0); bf16_split(v.y, h1, l1);
                bf16_split(v.z, h2, l2); bf16_split(v.w, h3, l3);
                int off = r * LDK + c4 * 4;
                *(uint2*)(sA_hi + off) = make_uint2((uint32_t)h0 | ((uint32_t)h1 << 16),
                                                    (uint32_t)h2 | ((uint32_t)h3 << 16));
                *(uint2*)(sA_lo + off) = make_uint2((uint32_t)l0 | ((uint32_t)l1 << 16),
                                                    (uint32_t)l2 | ((uint32_t)l3 << 16));
            }
        } else {
#pragma unroll
            for (int it = 0; it < 8; it++) {
                int idx = tid + it * 256;          // 2048 = 2 planes * 64 * 16 chunks
                int plane = idx >> 10, rem = idx & 1023;
                int r = rem >> 4, c = rem & 15;
                int gr = rowBase + r;
                uint4 v = make_uint4(0u, 0u, 0u, 0u);
                if (gr < N)
                    v = *(const uint4*)((plane ? Alo : Ahi) + (size_t)gr * 128 + c * 8);
                *(uint4*)((plane ? sA_lo : sA_hi) + r * LDK + c * 8) = v;
            }
        }
        __syncthreads();

        float acc[2][NT][4];
#pragma unroll
        for (int mt = 0; mt < 2; mt++)
#pragma unroll
            for (int nt = 0; nt < NT; nt++)
#pragma unroll
                for (int i = 0; i < 4; i++) acc[mt][nt][i] = 0.f;

        // ---- 8 uninterrupted k-steps ----
#pragma unroll
        for (int kt = 0; kt < 8; kt++) {
            int ka = kt * 16 + 2 * tig;
            uint32_t ah[2][4], al[2][4];
#pragma unroll
            for (int mt = 0; mt < 2; mt++) {
                int r = warpM * 32 + mt * 16 + grp;
                ah[mt][0] = *(const uint32_t*)(sA_hi + r       * LDK + ka);
                ah[mt][1] = *(const uint32_t*)(sA_hi + (r + 8) * LDK + ka);
                ah[mt][2] = *(const uint32_t*)(sA_hi + r       * LDK + ka + 8);
                ah[mt][3] = *(const uint32_t*)(sA_hi + (r + 8) * LDK + ka + 8);
                al[mt][0] = *(const uint32_t*)(sA_lo + r       * LDK + ka);
                al[mt][1] = *(const uint32_t*)(sA_lo + (r + 8) * LDK + ka);
                al[mt][2] = *(const uint32_t*)(sA_lo + r       * LDK + ka + 8);
                al[mt][3] = *(const uint32_t*)(sA_lo + (r + 8) * LDK + ka + 8);
            }
            uint32_t bh[NT][2], bl[NT][2];
#pragma unroll
            for (int nt = 0; nt < NT; nt++) {
                int n = warpN * (BN / 4) + nt * 8 + grp;
                bh[nt][0] = *(const uint32_t*)(sW + n * LDK + ka);
                bh[nt][1] = *(const uint32_t*)(sW + n * LDK + ka + 8);
                bl[nt][0] = *(const uint32_t*)(sW + (BN + n) * LDK + ka);
                bl[nt][1] = *(const uint32_t*)(sW + (BN + n) * LDK + ka + 8);
            }
#pragma unroll
            for (int mt = 0; mt < 2; mt++)
#pragma unroll
                for (int nt = 0; nt < NT; nt++) {
                    mma_bf16(acc[mt][nt], ah[mt], bh[nt]);
                    mma_bf16(acc[mt][nt], ah[mt], bl[nt]);
                    mma_bf16(acc[mt][nt], al[mt], bh[nt]);
                }
        }
        __syncthreads();   // frag reads done before next tile overwrites smem

        // ---- store C as fp16 ----
#pragma unroll
        for (int mt = 0; mt < 2; mt++) {
            int r0 = rowBase + warpM * 32 + mt * 16 + grp;
#pragma unroll
            for (int nt = 0; nt < NT; nt++) {
                int c = warpN * (BN / 4) + nt * 8 + tig * 2;
                if (r0 < N)
                    *(__half2*)(C + (size_t)r0 * BN + c) =
                        __floats2half2_rn(acc[mt][nt][0], acc[mt][nt][1]);
                if (r0 + 8 < N)
                    *(__half2*)(C + (size_t)(r0 + 8) * BN + c) =
                        __floats2half2_rn(acc[mt][nt][2], acc[mt][nt][3]);
            }
        }
    }
}

__global__ __launch_bounds__(256, 2) void gemm1_kernel(const float* __restrict__ x,
                                                       int N, int tiles) {
    gemm_body<128, true>(x, nullptr, nullptr, g_W1hi, g_W1lo, g_h1, N, tiles);
}
__global__ __launch_bounds__(256, 2) void gemm2_kernel(int N, int tiles) {
    gemm_body<64, false>(nullptr, g_Hhi, g_Hlo, g_W2hi, g_W2lo, g_h2, N, tiles);
}

// ================= CSR build =================
__global__ void zero_count_kernel(int N) {
    int i = blockIdx.x * blockDim.x + threadIdx.x;
    if (i < N) g_count[i] = 0;
}
__global__ void degree_kernel(const int* __restrict__ ei, int E, int N) {
    int e = blockIdx.x * blockDim.x + threadIdx.x;
    if (e >= E) return;
    int d = ei[E + e];
    int p = 0;
    if ((unsigned)d < (unsigned)N) p = atomicAdd(&g_count[d], 1);
    g_rank[e] = p;
}
__global__ void scan_partial_kernel(int N) {
    __shared__ int sh[256];
    int t = threadIdx.x, b = blockIdx.x;
    int i = b * 256 + t;
    sh[t] = (i < N) ? g_count[i] : 0;
    __syncthreads();
    for (int off = 128; off > 0; off >>= 1) {
        if (t < off) sh[t] += sh[t + off];
        __syncthreads();
    }
    if (t == 0) g_bsum[b] = sh[0];
}
__global__ void scan_blocks_kernel(int nb) {
    __shared__ int sh[256];
    int t = threadIdx.x;
    int v = (t < nb) ? g_bsum[t] : 0;
    sh[t] = v;
    __syncthreads();
    for (int off = 1; off < 256; off <<= 1) {
        int a = 0;
        if (t >= off) a = sh[t - off];
        __syncthreads();
        if (t >= off) sh[t] += a;
        __syncthreads();
    }
    if (t < nb) g_boff[t] = sh[t] - v;
}
__global__ void scan_final_kernel(int N) {
    __shared__ int sh[256];
    int t = threadIdx.x, b = blockIdx.x;
    int i = b * 256 + t;
    int c = (i < N) ? g_count[i] : 0;
    sh[t] = c;
    __syncthreads();
    for (int off = 1; off < 256; off <<= 1) {
        int a = 0;
        if (t >= off) a = sh[t - off];
        __syncthreads();
        if (t >= off) sh[t] += a;
        __syncthreads();
    }
    if (i < N) {
        int incl = sh[t] + g_boff[b];
        g_rowptr[i] = incl - c;
        g_dinv[i] = rsqrtf((float)c + 1.0f);
        if (i == N - 1) g_rowptr[N] = incl;
    }
}
__global__ void fill_csr_kernel(const int* __restrict__ ei, int E, int N) {
    int e = blockIdx.x * blockDim.x + threadIdx.x;
    if (e >= E) return;
    int s = ei[e];
    int d = ei[E + e];
    if ((unsigned)d >= (unsigned)N || (unsigned)s >= (unsigned)N) return;
    g_csr[g_rowptr[d] + g_rank[e]] = s;
}

// ================= gathers (fp16 reads, fp32 accumulate, unroll x4 for MLP) ==========
__global__ void gather128_kernel(const float* __restrict__ b1, int N) {
    int w    = (blockIdx.x * blockDim.x + threadIdx.x) >> 5;
    int lane = threadIdx.x & 31;
    if (w >= N) return;
    int beg = g_rowptr[w], end = g_rowptr[w + 1];
    float4 acc = make_float4(0.f, 0.f, 0.f, 0.f);
    int e = beg;
    for (; e + 3 < end; e += 4) {
        int s0 = g_csr[e],     s1 = g_csr[e + 1];
        int s2 = g_csr[e + 2], s3 = g_csr[e + 3];
        float w0 = g_dinv[s0], w1 = g_dinv[s1], w2 = g_dinv[s2], w3 = g_dinv[s3];
        float4 v0 = ld_half4(g_h1 + (size_t)s0 * 128 + lane * 4);
        float4 v1 = ld_half4(g_h1 + (size_t)s1 * 128 + lane * 4);
        float4 v2 = ld_half4(g_h1 + (size_t)s2 * 128 + lane * 4);
        float4 v3 = ld_half4(g_h1 + (size_t)s3 * 128 + lane * 4);
        acc.x += w0 * v0.x + w1 * v1.x + w2 * v2.x + w3 * v3.x;
        acc.y += w0 * v0.y + w1 * v1.y + w2 * v2.y + w3 * v3.y;
        acc.z += w0 * v0.z + w1 * v1.z + w2 * v2.z + w3 * v3.z;
        acc.w += w0 * v0.w + w1 * v1.w + w2 * v2.w + w3 * v3.w;
    }
    for (; e < end; e++) {
        int s0 = g_csr[e];
        float w0 = g_dinv[s0];
        float4 v0 = ld_half4(g_h1 + (size_t)s0 * 128 + lane * 4);
        acc.x += w0 * v0.x; acc.y += w0 * v0.y; acc.z += w0 * v0.z; acc.w += w0 * v0.w;
    }
    float dd = g_dinv[w];
    float d2 = dd * dd;
    float4 self = ld_half4(g_h1 + (size_t)w * 128 + lane * 4);
    float4 bv   = *(const float4*)(b1 + lane * 4);
    float4 r;
    r.x = fmaxf(dd * acc.x + d2 * self.x + bv.x, 0.f);
    r.y = fmaxf(dd * acc.y + d2 * self.y + bv.y, 0.f);
    r.z = fmaxf(dd * acc.z + d2 * self.z + bv.z, 0.f);
    r.w = fmaxf(dd * acc.w + d2 * self.w + bv.w, 0.f);
    unsigned short h0, h1v, h2v, h3, l0, l1v, l2v, l3;
    bf16_split(r.x, h0, l0); bf16_split(r.y, h1v, l1v);
    bf16_split(r.z, h2v, l2v); bf16_split(r.w, h3, l3);
    size_t off = (size_t)w * 128 + lane * 4;
    *(uint2*)(g_Hhi + off) = make_uint2((uint32_t)h0 | ((uint32_t)h1v << 16),
                                        (uint32_t)h2v | ((uint32_t)h3 << 16));
    *(uint2*)(g_Hlo + off) = make_uint2((uint32_t)l0 | ((uint32_t)l1v << 16),
                                        (uint32_t)l2v | ((uint32_t)l3 << 16));
}
__global__ void gather64_kernel(const float* __restrict__ b2, float* __restrict__ out, int N) {
    int w    = (blockIdx.x * blockDim.x + threadIdx.x) >> 5;
    int lane = threadIdx.x & 31;
    if (w >= N) return;
    int beg = g_rowptr[w], end = g_rowptr[w + 1];
    float2 acc = make_float2(0.f, 0.f);
    int e = beg;
    for (; e + 3 < end; e += 4) {
        int s0 = g_csr[e],     s1 = g_csr[e + 1];
        int s2 = g_csr[e + 2], s3 = g_csr[e + 3];
        float w0 = g_dinv[s0], w1 = g_dinv[s1], w2 = g_dinv[s2], w3 = g_dinv[s3];
        float2 v0 = __half22float2(*(const __half2*)(g_h2 + (size_t)s0 * 64 + lane * 2));
        float2 v1 = __half22float2(*(const __half2*)(g_h2 + (size_t)s1 * 64 + lane * 2));
        float2 v2 = __half22float2(*(const __half2*)(g_h2 + (size_t)s2 * 64 + lane * 2));
        float2 v3 = __half22float2(*(const __half2*)(g_h2 + (size_t)s3 * 64 + lane * 2));
        acc.x += w0 * v0.x + w1 * v1.x + w2 * v2.x + w3 * v3.x;
        acc.y += w0 * v0.y + w1 * v1.y + w2 * v2.y + w3 * v3.y;
    }
    for (; e < end; e++) {
        int s0 = g_csr[e];
        float w0 = g_dinv[s0];
        float2 v0 = __half22float2(*(const __half2*)(g_h2 + (size_t)s0 * 64 + lane * 2));
        acc.x += w0 * v0.x; acc.y += w0 * v0.y;
    }
    float dd = g_dinv[w];
    float d2 = dd * dd;
    float2 self = __half22float2(*(const __half2*)(g_h2 + (size_t)w * 64 + lane * 2));
    float2 bv   = *(const float2*)(b2 + lane * 2);
    float2 r;
    r.x = dd * acc.x + d2 * self.x + bv.x;
    r.y = dd * acc.y + d2 * self.y + bv.y;
    *(float2*)(out + (size_t)w * 64 + lane * 2) = r;
}

// ================= launch =================
extern "C" void kernel_launch(void* const* d_in, const int* in_sizes, int n_in,
                              void* d_out, int out_size) {
    const float* x  = (const float*)d_in[0];
    const int*   ei = (const int*)d_in[1];     // int32 (JAX x64 disabled)
    const float* W1 = (const float*)d_in[2];
    const float* b1 = (const float*)d_in[3];
    const float* W2 = (const float*)d_in[4];
    const float* b2 = (const float*)d_in[5];
    float* out = (float*)d_out;

    int N = in_sizes[0] / 128;
    int E = in_sizes[1] / 2;
    if (N > N_MAX) N = N_MAX;
    if (E > E_MAX) E = E_MAX;

    const int TPB = 256;
    int tiles = (N + 63) / 64;
    int nb    = (N + 255) / 256;

    constexpr int SMEM1 = (2 * 128 * 136 + 2 * 64 * 136) * 2;   // 104448 B -> 2 CTAs/SM
    constexpr int SMEM2 = (2 * 64  * 136 + 2 * 64 * 136) * 2;   //  69632 B -> 2 CTAs/SM
    cudaFuncSetAttribute(gemm1_kernel, cudaFuncAttributeMaxDynamicSharedMemorySize, SMEM1);
    cudaFuncSetAttribute(gemm2_kernel, cudaFuncAttributeMaxDynamicSharedMemorySize, SMEM2);

    // Dual-stream fork/join (graph-capturable); resources freed only when not capturing.
    cudaStream_t sB = 0;
    cudaStreamCreateWithFlags(&sB, cudaStreamNonBlocking);
    cudaEvent_t evF, evJ;
    cudaEventCreateWithFlags(&evF, cudaEventDisableTiming);
    cudaEventCreateWithFlags(&evJ, cudaEventDisableTiming);

    cudaEventRecord(evF, 0);
    cudaStreamWaitEvent(sB, evF, 0);

    // launch order keeps gemm1 as my 4th kernel launch (the ncu-profiled slot)
    zero_count_kernel<<<(N + TPB - 1) / TPB, TPB, 0, sB>>>(N);               // 0 (sB)
    degree_kernel<<<(E + TPB - 1) / TPB, TPB, 0, sB>>>(ei, E, N);            // 1 (sB)
    wsplit_kernel<<<(128 * 128 + TPB - 1) / TPB, TPB>>>(W1, 128, 0);         // 2 (s0)
    gemm1_kernel<<<296, 256, SMEM1>>>(x, N, tiles);                          // 3 (s0) <- profiled

    scan_partial_kernel<<<nb, 256, 0, sB>>>(N);                              // (sB)
    scan_blocks_kernel<<<1, 256, 0, sB>>>(nb);                               // (sB)
    scan_final_kernel<<<nb, 256, 0, sB>>>(N);                                // (sB)
    fill_csr_kernel<<<(E + TPB - 1) / TPB, TPB, 0, sB>>>(ei, E, N);          // (sB)
    wsplit_kernel<<<(128 * 64 + TPB - 1) / TPB, TPB, 0, sB>>>(W2, 64, 1);    // (sB)

    cudaEventRecord(evJ, sB);
    cudaStreamWaitEvent(0, evJ, 0);

    {
        long long tot = (long long)N * 32;
        gather128_kernel<<<(int)((tot + TPB - 1) / TPB), TPB>>>(b1, N);      // (s0)
    }
    gemm2_kernel<<<296, 256, SMEM2>>>(N, tiles);                             // (s0)
    {
        long long tot = (long long)N * 32;
        gather64_kernel<<<(int)((tot + TPB - 1) / TPB), TPB>>>(b2, out, N);  // (s0)
    }

    cudaStreamCaptureStatus cap = cudaStreamCaptureStatusNone;
    cudaStreamIsCapturing(sB, &cap);
    if (cap == cudaStreamCaptureStatusNone) {
        cudaEventDestroy(evF);
        cudaEventDestroy(evJ);
        cudaStreamDestroy(sB);
    }
}